// round 1
// baseline (speedup 1.0000x reference)
#include <cuda_runtime.h>
#include <cstdint>

#define NN   10000
#define EE   160000
#define CIN  1024
#define HID  1024
#define COUT 512
#define GN_EPS 1e-5f
#define SLOPE  0.1f

// ---------------- scratch (static device globals; no runtime alloc) ----------------
__device__ float g_buf1[(size_t)NN * HID];   // 40.96 MB
__device__ float g_buf2[(size_t)NN * HID];   // 40.96 MB
__device__ float g_alpha[CIN];
__device__ float g_beta[CIN];
__device__ float g_sum[CIN];
__device__ float g_sumsq[CIN];
__device__ float g_dinv[NN];
__device__ int   g_cnt[NN];
__device__ int   g_rowptr[NN + 1];
__device__ int   g_cur[NN];
__device__ int   g_srcs[EE];
__device__ int   g_dsts[EE];
__device__ int   g_cols[EE];
__device__ float g_wt[EE];
__device__ int   g_is64;

// ---------------- small utility kernels ----------------

__global__ void k_zero() {
    int i = blockIdx.x * blockDim.x + threadIdx.x;
    if (i < CIN) { g_sum[i] = 0.f; g_sumsq[i] = 0.f; }
    if (i < NN)  { g_cnt[i] = 0; }
}

// Detect whether edge_index is int64 or int32. Values are in [0, 10000), so
// for int64 every high 32-bit word is 0. For int32 data, 64 consecutive
// odd-position words being zero has probability ~1e-256.
__global__ void k_detect(const int* __restrict__ e) {
    if (threadIdx.x == 0 && blockIdx.x == 0) {
        int is64 = 1;
        for (int i = 0; i < 64; ++i)
            if (e[2 * i + 1] != 0) { is64 = 0; break; }
        g_is64 = is64;
    }
}

__global__ void k_convert(const void* __restrict__ edges) {
    int i = blockIdx.x * blockDim.x + threadIdx.x;
    if (i >= EE) return;
    int s, d;
    if (g_is64) {
        const long long* e = (const long long*)edges;
        s = (int)e[i];
        d = (int)e[EE + i];
    } else {
        const int* e = (const int*)edges;
        s = e[i];
        d = e[EE + i];
    }
    g_srcs[i] = s;
    g_dsts[i] = d;
}

__global__ void k_count() {
    int i = blockIdx.x * blockDim.x + threadIdx.x;
    if (i >= EE) return;
    atomicAdd(&g_cnt[g_dsts[i]], 1);
}

__global__ void k_dinv() {
    int i = blockIdx.x * blockDim.x + threadIdx.x;
    if (i >= NN) return;
    g_dinv[i] = rsqrtf((float)(g_cnt[i] + 1));   // +1 for self loop
}

// Single-block exclusive scan of g_cnt -> g_rowptr / g_cur (N = 10000).
__global__ void k_scan() {
    __shared__ int sh[1024];
    const int t = threadIdx.x;
    int run = 0;
    for (int base = 0; base < NN; base += 1024) {
        int idx = base + t;
        int v = (idx < NN) ? g_cnt[idx] : 0;
        sh[t] = v;
        __syncthreads();
        for (int off = 1; off < 1024; off <<= 1) {
            int add = (t >= off) ? sh[t - off] : 0;
            __syncthreads();
            sh[t] += add;
            __syncthreads();
        }
        if (idx < NN) {
            int ex = run + sh[t] - v;
            g_rowptr[idx] = ex;
            g_cur[idx]    = ex;
        }
        int tot = sh[1023];
        __syncthreads();
        run += tot;
    }
    if (t == 0) g_rowptr[NN] = run;
}

__global__ void k_fill() {
    int i = blockIdx.x * blockDim.x + threadIdx.x;
    if (i >= EE) return;
    int d = g_dsts[i];
    int s = g_srcs[i];
    int pos = atomicAdd(&g_cur[d], 1);
    g_cols[pos] = s;
    g_wt[pos]   = g_dinv[s] * g_dinv[d];
}

// Column sums / sumsq over x [NN x CIN].  Each block walks a strided set of
// rows; thread t owns columns t, t+256, t+512, t+768.
__global__ void k_stats(const float* __restrict__ x) {
    const int t = threadIdx.x;
    float s0 = 0.f, s1 = 0.f, s2 = 0.f, s3 = 0.f;
    float q0 = 0.f, q1 = 0.f, q2 = 0.f, q3 = 0.f;
    for (int r = blockIdx.x; r < NN; r += gridDim.x) {
        const float* row = x + (size_t)r * CIN;
        float v0 = row[t];       s0 += v0; q0 += v0 * v0;
        float v1 = row[t + 256]; s1 += v1; q1 += v1 * v1;
        float v2 = row[t + 512]; s2 += v2; q2 += v2 * v2;
        float v3 = row[t + 768]; s3 += v3; q3 += v3 * v3;
    }
    atomicAdd(&g_sum[t],         s0); atomicAdd(&g_sumsq[t],         q0);
    atomicAdd(&g_sum[t + 256],   s1); atomicAdd(&g_sumsq[t + 256],   q1);
    atomicAdd(&g_sum[t + 512],   s2); atomicAdd(&g_sumsq[t + 512],   q2);
    atomicAdd(&g_sum[t + 768],   s3); atomicAdd(&g_sumsq[t + 768],   q3);
}

// xn = (x - s*mean)*rstd*w + b  ==  x*alpha + beta
__global__ void k_fin(const float* __restrict__ gw,
                      const float* __restrict__ gb,
                      const float* __restrict__ gms) {
    int i = blockIdx.x * blockDim.x + threadIdx.x;
    if (i >= CIN) return;
    float mean = g_sum[i]   * (1.0f / NN);
    float ex2  = g_sumsq[i] * (1.0f / NN);
    float s    = gms[i];
    float var  = ex2 - 2.f * s * mean * mean + s * s * mean * mean;
    float rstd = rsqrtf(var + GN_EPS);
    float al   = rstd * gw[i];
    g_alpha[i] = al;
    g_beta[i]  = gb[i] - s * mean * al;
}

// ---------------- SGEMM: 128x128x16 tile, 256 thr, 8x8/thread, smem dbl-buf ----------------
// MODE 0: C(g_buf1) = affine(x) @ W1            (A = Aext, per-k alpha/beta fused into load)
// MODE 1: out = (g_buf1 @ [Wm|Ws]) + [bm|bs]    (writes z, mu, logstd)
template <int MODE>
__global__ void __launch_bounds__(256, 2)
k_gemm(const float* __restrict__ Aext,
       const float* __restrict__ B0, const float* __restrict__ B1,
       const float* __restrict__ bias0, const float* __restrict__ bias1,
       float* __restrict__ Cext) {
    constexpr int K  = CIN;
    constexpr int BM = 128, BN = 128, BK = 16;
    constexpr int NT = K / BK;

    __shared__ float As[2][BK][BM + 4];
    __shared__ float Bs[2][BK][BN];

    const float* A = (MODE == 0) ? Aext : g_buf1;
    const int M = NN;

    const int tid = threadIdx.x;
    const int tx  = tid & 15;
    const int ty  = tid >> 4;
    const int bn0 = blockIdx.x * BN;
    const int bm0 = blockIdx.y * BM;

    const float* Bp;
    int ldb, bcol;
    if (MODE == 0) { Bp = B0; ldb = HID; bcol = bn0; }
    else {
        ldb = COUT;
        if (bn0 < COUT) { Bp = B0; bcol = bn0; }
        else            { Bp = B1; bcol = bn0 - COUT; }
    }

    const int aRow = tid >> 2;          // 0..63
    const int aCol = (tid & 3) << 2;    // 0,4,8,12
    const int bRow = tid >> 5;          // 0..7
    const int bCol = (tid & 31) << 2;   // 0..124

    const int mA0 = bm0 + aRow;
    const int mA1 = mA0 + 64;

    float4 ar0, ar1, br0, br1;

    // ---- load tile 0 ----
    {
        const int k0 = 0;
        ar0 = make_float4(0.f, 0.f, 0.f, 0.f);
        ar1 = ar0;
        if (mA0 < M) ar0 = *(const float4*)(A + (size_t)mA0 * K + k0 + aCol);
        if (mA1 < M) ar1 = *(const float4*)(A + (size_t)mA1 * K + k0 + aCol);
        if (MODE == 0) {
            int k = k0 + aCol;
            float a0 = g_alpha[k], a1 = g_alpha[k + 1], a2 = g_alpha[k + 2], a3 = g_alpha[k + 3];
            float b0 = g_beta[k],  b1 = g_beta[k + 1],  b2 = g_beta[k + 2],  b3 = g_beta[k + 3];
            ar0.x = fmaf(ar0.x, a0, b0); ar0.y = fmaf(ar0.y, a1, b1);
            ar0.z = fmaf(ar0.z, a2, b2); ar0.w = fmaf(ar0.w, a3, b3);
            ar1.x = fmaf(ar1.x, a0, b0); ar1.y = fmaf(ar1.y, a1, b1);
            ar1.z = fmaf(ar1.z, a2, b2); ar1.w = fmaf(ar1.w, a3, b3);
        }
        br0 = *(const float4*)(Bp + (size_t)(k0 + bRow) * ldb + bcol + bCol);
        br1 = *(const float4*)(Bp + (size_t)(k0 + bRow + 8) * ldb + bcol + bCol);

        As[0][aCol + 0][aRow] = ar0.x; As[0][aCol + 1][aRow] = ar0.y;
        As[0][aCol + 2][aRow] = ar0.z; As[0][aCol + 3][aRow] = ar0.w;
        As[0][aCol + 0][aRow + 64] = ar1.x; As[0][aCol + 1][aRow + 64] = ar1.y;
        As[0][aCol + 2][aRow + 64] = ar1.z; As[0][aCol + 3][aRow + 64] = ar1.w;
        *(float4*)&Bs[0][bRow][bCol]     = br0;
        *(float4*)&Bs[0][bRow + 8][bCol] = br1;
    }
    __syncthreads();

    float acc[8][8];
#pragma unroll
    for (int i = 0; i < 8; ++i)
#pragma unroll
        for (int j = 0; j < 8; ++j) acc[i][j] = 0.f;

#pragma unroll 1
    for (int t = 0; t < NT; ++t) {
        const int cur = t & 1;
        if (t + 1 < NT) {
            const int k0 = (t + 1) * BK;
            ar0 = make_float4(0.f, 0.f, 0.f, 0.f);
            ar1 = ar0;
            if (mA0 < M) ar0 = *(const float4*)(A + (size_t)mA0 * K + k0 + aCol);
            if (mA1 < M) ar1 = *(const float4*)(A + (size_t)mA1 * K + k0 + aCol);
            if (MODE == 0) {
                int k = k0 + aCol;
                float a0 = g_alpha[k], a1 = g_alpha[k + 1], a2 = g_alpha[k + 2], a3 = g_alpha[k + 3];
                float b0 = g_beta[k],  b1 = g_beta[k + 1],  b2 = g_beta[k + 2],  b3 = g_beta[k + 3];
                ar0.x = fmaf(ar0.x, a0, b0); ar0.y = fmaf(ar0.y, a1, b1);
                ar0.z = fmaf(ar0.z, a2, b2); ar0.w = fmaf(ar0.w, a3, b3);
                ar1.x = fmaf(ar1.x, a0, b0); ar1.y = fmaf(ar1.y, a1, b1);
                ar1.z = fmaf(ar1.z, a2, b2); ar1.w = fmaf(ar1.w, a3, b3);
            }
            br0 = *(const float4*)(Bp + (size_t)(k0 + bRow) * ldb + bcol + bCol);
            br1 = *(const float4*)(Bp + (size_t)(k0 + bRow + 8) * ldb + bcol + bCol);
        }

#pragma unroll
        for (int kk = 0; kk < BK; ++kk) {
            float4 a0 = *(const float4*)&As[cur][kk][ty * 8];
            float4 a1 = *(const float4*)&As[cur][kk][ty * 8 + 4];
            float4 b0 = *(const float4*)&Bs[cur][kk][tx * 8];
            float4 b1 = *(const float4*)&Bs[cur][kk][tx * 8 + 4];
            float a[8] = {a0.x, a0.y, a0.z, a0.w, a1.x, a1.y, a1.z, a1.w};
            float b[8] = {b0.x, b0.y, b0.z, b0.w, b1.x, b1.y, b1.z, b1.w};
#pragma unroll
            for (int i = 0; i < 8; ++i)
#pragma unroll
                for (int j = 0; j < 8; ++j)
                    acc[i][j] = fmaf(a[i], b[j], acc[i][j]);
        }

        if (t + 1 < NT) {
            const int nxt = (t + 1) & 1;
            As[nxt][aCol + 0][aRow] = ar0.x; As[nxt][aCol + 1][aRow] = ar0.y;
            As[nxt][aCol + 2][aRow] = ar0.z; As[nxt][aCol + 3][aRow] = ar0.w;
            As[nxt][aCol + 0][aRow + 64] = ar1.x; As[nxt][aCol + 1][aRow + 64] = ar1.y;
            As[nxt][aCol + 2][aRow + 64] = ar1.z; As[nxt][aCol + 3][aRow + 64] = ar1.w;
            *(float4*)&Bs[nxt][bRow][bCol]     = br0;
            *(float4*)&Bs[nxt][bRow + 8][bCol] = br1;
            __syncthreads();
        }
    }

    // ---- epilogue ----
#pragma unroll
    for (int i = 0; i < 8; ++i) {
        int m = bm0 + ty * 8 + i;
        if (m >= M) continue;
        if (MODE == 0) {
            float* dst = g_buf1 + (size_t)m * HID + bn0 + tx * 8;
            float4 v0 = make_float4(acc[i][0], acc[i][1], acc[i][2], acc[i][3]);
            float4 v1 = make_float4(acc[i][4], acc[i][5], acc[i][6], acc[i][7]);
            *(float4*)dst       = v0;
            *(float4*)(dst + 4) = v1;
        } else {
            int nc = bcol + tx * 8;   // column within [0,512)
            const float* bia = (bn0 < COUT) ? bias0 : bias1;
            float v[8];
#pragma unroll
            for (int j = 0; j < 8; ++j) v[j] = acc[i][j] + bia[nc + j];
            float4 v0 = make_float4(v[0], v[1], v[2], v[3]);
            float4 v1 = make_float4(v[4], v[5], v[6], v[7]);
            if (bn0 < COUT) {
                float* d0 = Cext + (size_t)m * COUT + nc;                        // z
                float* d1 = Cext + (size_t)NN * COUT + (size_t)m * COUT + nc;    // mu
                *(float4*)d0 = v0; *(float4*)(d0 + 4) = v1;
                *(float4*)d1 = v0; *(float4*)(d1 + 4) = v1;
            } else {
                float* d2 = Cext + (size_t)2 * NN * COUT + (size_t)m * COUT + nc; // logstd
                *(float4*)d2 = v0; *(float4*)(d2 + 4) = v1;
            }
        }
    }
}

// ---------------- aggregation: out[i] = sum_e wt*in[col] + dinv[i]^2 * in[i] ----------------
// dir 0: in=g_buf1 out=g_buf2 (apply bias + leaky relu); dir 1: in=g_buf2 out=g_buf1 (plain).
__global__ void __launch_bounds__(256)
k_agg(int dir, const float* __restrict__ bias, int act) {
    const float* in  = dir ? g_buf2 : g_buf1;
    float*       out = dir ? g_buf1 : g_buf2;

    const int i = blockIdx.x;
    const int t = threadIdx.x;
    const float dv = g_dinv[i];
    const float sw = dv * dv;

    const float* selfrow = in + (size_t)i * HID;
    float a0 = sw * selfrow[t];
    float a1 = sw * selfrow[t + 256];
    float a2 = sw * selfrow[t + 512];
    float a3 = sw * selfrow[t + 768];

    const int beg = g_rowptr[i];
    const int end = g_rowptr[i + 1];
    for (int e = beg; e < end; ++e) {
        const int   s = g_cols[e];
        const float w = g_wt[e];
        const float* r = in + (size_t)s * HID;
        a0 = fmaf(w, r[t],       a0);
        a1 = fmaf(w, r[t + 256], a1);
        a2 = fmaf(w, r[t + 512], a2);
        a3 = fmaf(w, r[t + 768], a3);
    }

    if (act) {
        a0 += bias[t];       a0 = (a0 > 0.f) ? a0 : SLOPE * a0;
        a1 += bias[t + 256]; a1 = (a1 > 0.f) ? a1 : SLOPE * a1;
        a2 += bias[t + 512]; a2 = (a2 > 0.f) ? a2 : SLOPE * a2;
        a3 += bias[t + 768]; a3 = (a3 > 0.f) ? a3 : SLOPE * a3;
    }

    float* o = out + (size_t)i * HID;
    o[t]       = a0;
    o[t + 256] = a1;
    o[t + 512] = a2;
    o[t + 768] = a3;
}

// ---------------- launch ----------------
extern "C" void kernel_launch(void* const* d_in, const int* in_sizes, int n_in,
                              void* d_out, int out_size) {
    const float* x   = (const float*)d_in[0];
    const void*  edg = d_in[1];
    const float* W1  = (const float*)d_in[2];
    const float* b1  = (const float*)d_in[3];
    const float* Wm  = (const float*)d_in[4];
    const float* bm  = (const float*)d_in[5];
    const float* Ws  = (const float*)d_in[6];
    const float* bs  = (const float*)d_in[7];
    const float* gw  = (const float*)d_in[8];
    const float* gb  = (const float*)d_in[9];
    const float* gms = (const float*)d_in[10];
    float* out = (float*)d_out;

    // graph preprocessing + norm stats
    k_zero<<<(NN + 255) / 256, 256>>>();
    k_detect<<<1, 1>>>((const int*)edg);
    k_convert<<<(EE + 255) / 256, 256>>>(edg);
    k_count<<<(EE + 255) / 256, 256>>>();
    k_dinv<<<(NN + 255) / 256, 256>>>();
    k_scan<<<1, 1024>>>();
    k_fill<<<(EE + 255) / 256, 256>>>();
    k_stats<<<200, 256>>>(x);
    k_fin<<<(CIN + 255) / 256, 256>>>(gw, gb, gms);

    // layer 1: buf1 = graphnorm(x) @ W1
    dim3 g1(HID / 128, (NN + 127) / 128);
    k_gemm<0><<<g1, 256>>>(x, W1, nullptr, nullptr, nullptr, nullptr);

    // buf2 = leakyrelu(A_norm @ buf1 + b1)
    k_agg<<<NN, 256>>>(0, b1, 1);
    // buf1 = A_norm @ buf2
    k_agg<<<NN, 256>>>(1, nullptr, 0);

    // layer 2: out = buf1 @ [Wm|Ws] + [bm|bs]   (z = mu duplicated)
    dim3 g2((2 * COUT) / 128, (NN + 127) / 128);
    k_gemm<1><<<g2, 256>>>(nullptr, Wm, Ws, bm, bs, out);
}

// round 3
// speedup vs baseline: 1.8709x; 1.8709x over previous
#include <cuda_runtime.h>
#include <cuda_bf16.h>
#include <cstdint>

#define NN   10000
#define EE   160000
#define CIN  1024
#define HID  1024
#define COUT 512
#define KEXP 3072            // 3 * 1024 (bf16 split K-expansion)
#define MPAD 10112           // 79 * 128
#define GN_EPS 1e-5f
#define SLOPE  0.1f

// ---------------- scratch (static device globals; no runtime alloc) ----------------
__device__ float g_buf1[(size_t)NN * HID];            // h  (f32)
__device__ float g_buf2[(size_t)NN * HID];            // agg1 out (f32)
__device__ __nv_bfloat16 g_a1[(size_t)MPAD * KEXP];   // GEMM1 A'' (split bf16)
__device__ __nv_bfloat16 g_a2[(size_t)MPAD * KEXP];   // GEMM2 A''
__device__ __nv_bfloat16 g_b1[(size_t)KEXP * HID];    // GEMM1 B'' = split(W1)
__device__ __nv_bfloat16 g_b2[(size_t)KEXP * HID];    // GEMM2 B'' = split([Wm|Ws])
__device__ float g_alpha[CIN];
__device__ float g_beta[CIN];
__device__ float g_sum[CIN];
__device__ float g_sumsq[CIN];
__device__ float g_dinv[NN];
__device__ int   g_cnt[NN];
__device__ int   g_rowptr[NN + 1];
__device__ int   g_cur[NN];
__device__ int   g_srcs[EE];
__device__ int   g_dsts[EE];
__device__ int   g_cols[EE];
__device__ float g_wt[EE];
__device__ int   g_is64;

// ---------------- PTX helpers ----------------
__device__ __forceinline__ void cpa16(void* dst, const void* src) {
    unsigned d = (unsigned)__cvta_generic_to_shared(dst);
    asm volatile("cp.async.cg.shared.global [%0], [%1], 16;" :: "r"(d), "l"(src) : "memory");
}
__device__ __forceinline__ void ldsm4(unsigned* r, const void* p) {
    unsigned a = (unsigned)__cvta_generic_to_shared(p);
    asm volatile("ldmatrix.sync.aligned.m8n8.x4.shared.b16 {%0,%1,%2,%3}, [%4];"
                 : "=r"(r[0]), "=r"(r[1]), "=r"(r[2]), "=r"(r[3]) : "r"(a));
}
__device__ __forceinline__ void ldsm4t(unsigned* r, const void* p) {
    unsigned a = (unsigned)__cvta_generic_to_shared(p);
    asm volatile("ldmatrix.sync.aligned.m8n8.x4.trans.shared.b16 {%0,%1,%2,%3}, [%4];"
                 : "=r"(r[0]), "=r"(r[1]), "=r"(r[2]), "=r"(r[3]) : "r"(a));
}
__device__ __forceinline__ void mma16816(float* d, const unsigned* a, const unsigned* b) {
    asm volatile("mma.sync.aligned.m16n8k16.row.col.f32.bf16.bf16.f32 "
                 "{%0,%1,%2,%3}, {%4,%5,%6,%7}, {%8,%9}, {%0,%1,%2,%3};"
                 : "+f"(d[0]), "+f"(d[1]), "+f"(d[2]), "+f"(d[3])
                 : "r"(a[0]), "r"(a[1]), "r"(a[2]), "r"(a[3]), "r"(b[0]), "r"(b[1]));
}
__device__ __forceinline__ void bsplit(float v, __nv_bfloat16& b, __nv_bfloat16& s) {
    b = __float2bfloat16(v);
    s = __float2bfloat16(v - __bfloat162float(b));
}

// ---------------- small utility kernels ----------------
__global__ void k_zero() {
    int i = blockIdx.x * blockDim.x + threadIdx.x;
    if (i < CIN) { g_sum[i] = 0.f; g_sumsq[i] = 0.f; }
    if (i < NN)  { g_cnt[i] = 0; }
}

__global__ void k_detect(const int* __restrict__ e) {
    if (threadIdx.x == 0 && blockIdx.x == 0) {
        int is64 = 1;
        for (int i = 0; i < 64; ++i)
            if (e[2 * i + 1] != 0) { is64 = 0; break; }
        g_is64 = is64;
    }
}

__global__ void k_convert(const void* __restrict__ edges) {
    int i = blockIdx.x * blockDim.x + threadIdx.x;
    if (i >= EE) return;
    int s, d;
    if (g_is64) {
        const long long* e = (const long long*)edges;
        s = (int)e[i];  d = (int)e[EE + i];
    } else {
        const int* e = (const int*)edges;
        s = e[i];  d = e[EE + i];
    }
    g_srcs[i] = s;  g_dsts[i] = d;
}

__global__ void k_count() {
    int i = blockIdx.x * blockDim.x + threadIdx.x;
    if (i >= EE) return;
    atomicAdd(&g_cnt[g_dsts[i]], 1);
}

__global__ void k_dinv() {
    int i = blockIdx.x * blockDim.x + threadIdx.x;
    if (i >= NN) return;
    g_dinv[i] = rsqrtf((float)(g_cnt[i] + 1));
}

__global__ void k_scan() {
    __shared__ int sh[1024];
    const int t = threadIdx.x;
    int run = 0;
    for (int base = 0; base < NN; base += 1024) {
        int idx = base + t;
        int v = (idx < NN) ? g_cnt[idx] : 0;
        sh[t] = v;
        __syncthreads();
        for (int off = 1; off < 1024; off <<= 1) {
            int add = (t >= off) ? sh[t - off] : 0;
            __syncthreads();
            sh[t] += add;
            __syncthreads();
        }
        if (idx < NN) {
            int ex = run + sh[t] - v;
            g_rowptr[idx] = ex;
            g_cur[idx]    = ex;
        }
        int tot = sh[1023];
        __syncthreads();
        run += tot;
    }
    if (t == 0) g_rowptr[NN] = run;
}

__global__ void k_fill() {
    int i = blockIdx.x * blockDim.x + threadIdx.x;
    if (i >= EE) return;
    int d = g_dsts[i];
    int s = g_srcs[i];
    int pos = atomicAdd(&g_cur[d], 1);
    g_cols[pos] = s;
    g_wt[pos]   = g_dinv[s] * g_dinv[d];
}

__global__ void k_stats(const float* __restrict__ x) {
    const int t = threadIdx.x;
    float s0 = 0.f, s1 = 0.f, s2 = 0.f, s3 = 0.f;
    float q0 = 0.f, q1 = 0.f, q2 = 0.f, q3 = 0.f;
    for (int r = blockIdx.x; r < NN; r += gridDim.x) {
        const float* row = x + (size_t)r * CIN;
        float v0 = row[t];       s0 += v0; q0 += v0 * v0;
        float v1 = row[t + 256]; s1 += v1; q1 += v1 * v1;
        float v2 = row[t + 512]; s2 += v2; q2 += v2 * v2;
        float v3 = row[t + 768]; s3 += v3; q3 += v3 * v3;
    }
    atomicAdd(&g_sum[t],       s0); atomicAdd(&g_sumsq[t],       q0);
    atomicAdd(&g_sum[t + 256], s1); atomicAdd(&g_sumsq[t + 256], q1);
    atomicAdd(&g_sum[t + 512], s2); atomicAdd(&g_sumsq[t + 512], q2);
    atomicAdd(&g_sum[t + 768], s3); atomicAdd(&g_sumsq[t + 768], q3);
}

__global__ void k_fin(const float* __restrict__ gw,
                      const float* __restrict__ gb,
                      const float* __restrict__ gms) {
    int i = blockIdx.x * blockDim.x + threadIdx.x;
    if (i >= CIN) return;
    float mean = g_sum[i]   * (1.0f / NN);
    float ex2  = g_sumsq[i] * (1.0f / NN);
    float s    = gms[i];
    float var  = ex2 - 2.f * s * mean * mean + s * s * mean * mean;
    float rstd = rsqrtf(var + GN_EPS);
    float al   = rstd * gw[i];
    g_alpha[i] = al;
    g_beta[i]  = gb[i] - s * mean * al;
}

// Build A1'' = split(affine(x)) : [M][3K] = [big | small | big]
__global__ void k_build_a1(const float* __restrict__ x) {
    int i = blockIdx.x * blockDim.x + threadIdx.x;
    if (i >= NN * CIN) return;
    int m = i >> 10, k = i & 1023;
    float v = fmaf(x[i], g_alpha[k], g_beta[k]);
    __nv_bfloat16 b, s;
    bsplit(v, b, s);
    size_t base = (size_t)m * KEXP;
    g_a1[base + k]        = b;
    g_a1[base + 1024 + k] = s;
    g_a1[base + 2048 + k] = b;
}

// Build B1'' / B2'' : [3K][N] = [big ; big ; small]
__global__ void k_build_w(const float* __restrict__ W1,
                          const float* __restrict__ Wm,
                          const float* __restrict__ Ws) {
    int i = blockIdx.x * blockDim.x + threadIdx.x;
    if (i >= CIN * HID) return;
    int k = i >> 10, n = i & 1023;
    {
        __nv_bfloat16 b, s;
        bsplit(W1[i], b, s);
        g_b1[(size_t)k * HID + n]           = b;
        g_b1[(size_t)(k + 1024) * HID + n]  = b;
        g_b1[(size_t)(k + 2048) * HID + n]  = s;
    }
    {
        float w = (n < COUT) ? Wm[(size_t)k * COUT + n] : Ws[(size_t)k * COUT + n - COUT];
        __nv_bfloat16 b, s;
        bsplit(w, b, s);
        g_b2[(size_t)k * HID + n]           = b;
        g_b2[(size_t)(k + 1024) * HID + n]  = b;
        g_b2[(size_t)(k + 2048) * HID + n]  = s;
    }
}

// ---------------- bf16 tensor-core GEMM: 128x128 block, K=3072, cp.async dbl-buf ----------------
// A/B operands are selected INSIDE device code from MODE (device symbols must
// never be passed as kernel arguments from host — that was R2's bug).
// MODE 0: g_buf1 = g_a1'' @ g_b1''                  (h, f32)
// MODE 1: out    = g_a2'' @ g_b2'' + [bm|bs]        (z, mu, logstd)
template <int MODE>
__global__ void __launch_bounds__(256, 2)
k_mma(const float* __restrict__ bias0, const float* __restrict__ bias1,
      float* __restrict__ Cout)
{
    const __nv_bfloat16* __restrict__ A = (MODE == 0) ? g_a1 : g_a2;
    const __nv_bfloat16* __restrict__ B = (MODE == 0) ? g_b1 : g_b2;

    __shared__ __nv_bfloat16 sA[2][128][40];    // row pad 32->40: conflict-free LDSM
    __shared__ __nv_bfloat16 sB[2][32][136];    // row pad 128->136

    const int tid  = threadIdx.x;
    const int warp = tid >> 5;
    const int lane = tid & 31;
    const int bm0  = blockIdx.y * 128;
    const int bn0  = blockIdx.x * 128;

    // stage-copy thread mapping
    const int arow  = tid >> 1;        // 0..127
    const int ahalf = tid & 1;         // 16-bf16 half within BK=32
    const int brow  = tid >> 3;        // 0..31
    const int bc    = tid & 7;         // 8-bf16 chunk

    const __nv_bfloat16* aSrc = A + (size_t)(bm0 + arow) * KEXP + ahalf * 16;
    const __nv_bfloat16* bSrc = B + (size_t)brow * HID + bn0 + bc * 8;

    #define STAGE_COPY(st, it)  do {                                        \
        const __nv_bfloat16* as_ = aSrc + (it) * 32;                        \
        cpa16(&sA[(st)][arow][ahalf * 16],     as_);                        \
        cpa16(&sA[(st)][arow][ahalf * 16 + 8], as_ + 8);                    \
        const __nv_bfloat16* bs_ = bSrc + (size_t)(it) * 32 * HID;          \
        cpa16(&sB[(st)][brow][bc * 8],      bs_);                           \
        cpa16(&sB[(st)][brow][bc * 8 + 64], bs_ + 64);                      \
    } while (0)

    const int mbase = (warp >> 2) * 64;   // warp tile 64x32
    const int nbase = (warp & 3) * 32;
    const int lrow  = (lane & 7) + (lane & 8);
    const int lcol  = (lane >> 4) << 3;

    float acc[4][4][4];
    #pragma unroll
    for (int a = 0; a < 4; ++a)
        #pragma unroll
        for (int b = 0; b < 4; ++b)
            #pragma unroll
            for (int c = 0; c < 4; ++c) acc[a][b][c] = 0.f;

    STAGE_COPY(0, 0);
    asm volatile("cp.async.commit_group;" ::: "memory");

    const int NIT = KEXP / 32;   // 96
    #pragma unroll 1
    for (int it = 0; it < NIT; ++it) {
        const int cur = it & 1;
        if (it + 1 < NIT) {
            STAGE_COPY((it + 1) & 1, it + 1);
            asm volatile("cp.async.commit_group;" ::: "memory");
            asm volatile("cp.async.wait_group 1;" ::: "memory");
        } else {
            asm volatile("cp.async.wait_group 0;" ::: "memory");
        }
        __syncthreads();

        #pragma unroll
        for (int ks = 0; ks < 32; ks += 16) {
            unsigned af[4][4];
            #pragma unroll
            for (int mt = 0; mt < 4; ++mt)
                ldsm4(af[mt], &sA[cur][mbase + mt * 16 + lrow][ks + lcol]);
            unsigned bf[4][2];
            #pragma unroll
            for (int ntp = 0; ntp < 2; ++ntp) {
                unsigned t4[4];
                ldsm4t(t4, &sB[cur][ks + lrow][nbase + ntp * 16 + lcol]);
                bf[ntp * 2][0] = t4[0];  bf[ntp * 2][1] = t4[1];
                bf[ntp * 2 + 1][0] = t4[2];  bf[ntp * 2 + 1][1] = t4[3];
            }
            #pragma unroll
            for (int mt = 0; mt < 4; ++mt)
                #pragma unroll
                for (int nt = 0; nt < 4; ++nt)
                    mma16816(acc[mt][nt], af[mt], bf[nt]);
        }
        __syncthreads();
    }

    // ---- epilogue ----
    const int g  = lane >> 2;
    const int tg = lane & 3;
    #pragma unroll
    for (int mt = 0; mt < 4; ++mt) {
        #pragma unroll
        for (int nt = 0; nt < 4; ++nt) {
            int r0 = bm0 + mbase + mt * 16 + g;
            int r1 = r0 + 8;
            int c  = bn0 + nbase + nt * 8 + tg * 2;
            float* a4 = acc[mt][nt];
            if (MODE == 0) {
                if (r0 < NN) *(float2*)&g_buf1[(size_t)r0 * HID + c] = make_float2(a4[0], a4[1]);
                if (r1 < NN) *(float2*)&g_buf1[(size_t)r1 * HID + c] = make_float2(a4[2], a4[3]);
            } else {
                if (c < COUT) {
                    float2 v0 = make_float2(a4[0] + bias0[c], a4[1] + bias0[c + 1]);
                    float2 v1 = make_float2(a4[2] + bias0[c], a4[3] + bias0[c + 1]);
                    if (r0 < NN) {
                        *(float2*)&Cout[(size_t)r0 * COUT + c] = v0;                       // z
                        *(float2*)&Cout[(size_t)(NN + r0) * COUT + c] = v0;                // mu
                    }
                    if (r1 < NN) {
                        *(float2*)&Cout[(size_t)r1 * COUT + c] = v1;
                        *(float2*)&Cout[(size_t)(NN + r1) * COUT + c] = v1;
                    }
                } else {
                    int cs = c - COUT;
                    float2 v0 = make_float2(a4[0] + bias1[cs], a4[1] + bias1[cs + 1]);
                    float2 v1 = make_float2(a4[2] + bias1[cs], a4[3] + bias1[cs + 1]);
                    if (r0 < NN) *(float2*)&Cout[(size_t)(2 * NN + r0) * COUT + cs] = v0;  // logstd
                    if (r1 < NN) *(float2*)&Cout[(size_t)(2 * NN + r1) * COUT + cs] = v1;
                }
            }
        }
    }
    #undef STAGE_COPY
}

// ---------------- aggregation ----------------
// agg1: g_buf2 = leakyrelu(A_norm @ g_buf1 + b1)   (f32 out)
__global__ void __launch_bounds__(256)
k_agg1(const float* __restrict__ bias) {
    const int i = blockIdx.x;
    const int t = threadIdx.x;
    const float dv = g_dinv[i];
    const float sw = dv * dv;

    const float* selfrow = g_buf1 + (size_t)i * HID;
    float a0 = sw * selfrow[t];
    float a1 = sw * selfrow[t + 256];
    float a2 = sw * selfrow[t + 512];
    float a3 = sw * selfrow[t + 768];

    const int beg = g_rowptr[i];
    const int end = g_rowptr[i + 1];
    #pragma unroll 2
    for (int e = beg; e < end; ++e) {
        const int   s = g_cols[e];
        const float w = g_wt[e];
        const float* r = g_buf1 + (size_t)s * HID;
        a0 = fmaf(w, r[t],       a0);
        a1 = fmaf(w, r[t + 256], a1);
        a2 = fmaf(w, r[t + 512], a2);
        a3 = fmaf(w, r[t + 768], a3);
    }
    a0 += bias[t];       a0 = (a0 > 0.f) ? a0 : SLOPE * a0;
    a1 += bias[t + 256]; a1 = (a1 > 0.f) ? a1 : SLOPE * a1;
    a2 += bias[t + 512]; a2 = (a2 > 0.f) ? a2 : SLOPE * a2;
    a3 += bias[t + 768]; a3 = (a3 > 0.f) ? a3 : SLOPE * a3;

    float* o = g_buf2 + (size_t)i * HID;
    o[t] = a0;  o[t + 256] = a1;  o[t + 512] = a2;  o[t + 768] = a3;
}

// agg2: g_a2'' = split(A_norm @ g_buf2)   (bf16 split out, GEMM2 input)
__global__ void __launch_bounds__(256)
k_agg2() {
    const int i = blockIdx.x;
    const int t = threadIdx.x;
    const float dv = g_dinv[i];
    const float sw = dv * dv;

    const float* selfrow = g_buf2 + (size_t)i * HID;
    float a0 = sw * selfrow[t];
    float a1 = sw * selfrow[t + 256];
    float a2 = sw * selfrow[t + 512];
    float a3 = sw * selfrow[t + 768];

    const int beg = g_rowptr[i];
    const int end = g_rowptr[i + 1];
    #pragma unroll 2
    for (int e = beg; e < end; ++e) {
        const int   s = g_cols[e];
        const float w = g_wt[e];
        const float* r = g_buf2 + (size_t)s * HID;
        a0 = fmaf(w, r[t],       a0);
        a1 = fmaf(w, r[t + 256], a1);
        a2 = fmaf(w, r[t + 512], a2);
        a3 = fmaf(w, r[t + 768], a3);
    }

    __nv_bfloat16* o = g_a2 + (size_t)i * KEXP;
    __nv_bfloat16 b, s;
    bsplit(a0, b, s); o[t]       = b; o[1024 + t]       = s; o[2048 + t]       = b;
    bsplit(a1, b, s); o[t + 256] = b; o[1024 + t + 256] = s; o[2048 + t + 256] = b;
    bsplit(a2, b, s); o[t + 512] = b; o[1024 + t + 512] = s; o[2048 + t + 512] = b;
    bsplit(a3, b, s); o[t + 768] = b; o[1024 + t + 768] = s; o[2048 + t + 768] = b;
}

// ---------------- launch ----------------
extern "C" void kernel_launch(void* const* d_in, const int* in_sizes, int n_in,
                              void* d_out, int out_size) {
    const float* x   = (const float*)d_in[0];
    const void*  edg = d_in[1];
    const float* W1  = (const float*)d_in[2];
    const float* b1  = (const float*)d_in[3];
    const float* Wm  = (const float*)d_in[4];
    const float* bm  = (const float*)d_in[5];
    const float* Ws  = (const float*)d_in[6];
    const float* bs  = (const float*)d_in[7];
    const float* gw  = (const float*)d_in[8];
    const float* gb  = (const float*)d_in[9];
    const float* gms = (const float*)d_in[10];
    float* out = (float*)d_out;

    // graph preprocessing + norm stats
    k_zero<<<(NN + 255) / 256, 256>>>();
    k_detect<<<1, 1>>>((const int*)edg);
    k_convert<<<(EE + 255) / 256, 256>>>(edg);
    k_count<<<(EE + 255) / 256, 256>>>();
    k_dinv<<<(NN + 255) / 256, 256>>>();
    k_scan<<<1, 1024>>>();
    k_fill<<<(EE + 255) / 256, 256>>>();
    k_stats<<<200, 256>>>(x);
    k_fin<<<(CIN + 255) / 256, 256>>>(gw, gb, gms);

    // bf16-split operand construction
    k_build_a1<<<(NN * CIN + 255) / 256, 256>>>(x);
    k_build_w<<<(CIN * HID + 255) / 256, 256>>>(W1, Wm, Ws);

    // layer 1: h = graphnorm(x) @ W1   (tensor cores, bf16x3)
    dim3 g1(HID / 128, MPAD / 128);
    k_mma<0><<<g1, 256>>>(nullptr, nullptr, nullptr);

    // buf2 = leakyrelu(A_norm @ h + b1);  a2'' = split(A_norm @ buf2)
    k_agg1<<<NN, 256>>>(b1);
    k_agg2<<<NN, 256>>>();

    // layer 2: out = a2'' @ [Wm|Ws] + [bm|bs]   (z = mu duplicated)
    dim3 g2(HID / 128, MPAD / 128);
    k_mma<1><<<g2, 256>>>(bm, bs, out);
}

// round 5
// speedup vs baseline: 2.4441x; 1.3064x over previous
#include <cuda_runtime.h>
#include <cuda_fp16.h>
#include <cstdint>

#define NN   10000
#define EE   160000
#define CIN  1024
#define HID  1024
#define COUT 512
#define KH   1024            // K per plane
#define KEXP 2048            // 2 planes (fp16 split: [big | small])
#define MPAD 10112           // 79 * 128
#define GN_EPS 1e-5f
#define SLOPE  0.1f

// ---------------- scratch (static device globals; no runtime alloc) ----------------
__device__ float g_buf1[(size_t)NN * HID];          // h  (f32)
__device__ float g_buf2[(size_t)NN * HID];          // agg1 out (f32)
__device__ __half g_a1h[(size_t)MPAD * KEXP];       // GEMM1 A'' (fp16 2-plane, K-major)
__device__ __half g_a2h[(size_t)MPAD * KEXP];       // GEMM2 A''
__device__ __half g_b1h[(size_t)KH * HID];          // GEMM1 B big plane [k][n]
__device__ __half g_b2h[(size_t)KH * HID];          // GEMM2 B big plane [k][n] = [Wm|Ws]
__device__ float g_alpha[CIN];
__device__ float g_beta[CIN];
__device__ float g_sum[CIN];
__device__ float g_sumsq[CIN];
__device__ float g_dinv[NN];
__device__ int   g_cnt[NN];
__device__ int   g_rowptr[NN + 1];
__device__ int   g_cur[NN];
__device__ int   g_srcs[EE];
__device__ int   g_dsts[EE];
__device__ int   g_cols[EE];
__device__ float g_wt[EE];
__device__ int   g_is64;

// ---------------- PTX helpers ----------------
__device__ __forceinline__ unsigned smem_u32(const void* p) {
    return (unsigned)__cvta_generic_to_shared(p);
}
__device__ __forceinline__ void cpa16s(unsigned dst, const void* src) {
    asm volatile("cp.async.cg.shared.global [%0], [%1], 16;" :: "r"(dst), "l"(src) : "memory");
}
__device__ __forceinline__ void ldsm4(unsigned* r, const void* p) {
    unsigned a = smem_u32(p);
    asm volatile("ldmatrix.sync.aligned.m8n8.x4.shared.b16 {%0,%1,%2,%3}, [%4];"
                 : "=r"(r[0]), "=r"(r[1]), "=r"(r[2]), "=r"(r[3]) : "r"(a));
}
__device__ __forceinline__ void ldsm4t(unsigned* r, const void* p) {
    unsigned a = smem_u32(p);
    asm volatile("ldmatrix.sync.aligned.m8n8.x4.trans.shared.b16 {%0,%1,%2,%3}, [%4];"
                 : "=r"(r[0]), "=r"(r[1]), "=r"(r[2]), "=r"(r[3]) : "r"(a));
}
__device__ __forceinline__ void mma16816h(float* d, const unsigned* a, const unsigned* b) {
    asm volatile("mma.sync.aligned.m16n8k16.row.col.f32.f16.f16.f32 "
                 "{%0,%1,%2,%3}, {%4,%5,%6,%7}, {%8,%9}, {%0,%1,%2,%3};"
                 : "+f"(d[0]), "+f"(d[1]), "+f"(d[2]), "+f"(d[3])
                 : "r"(a[0]), "r"(a[1]), "r"(a[2]), "r"(a[3]), "r"(b[0]), "r"(b[1]));
}
__device__ __forceinline__ void hsplit(float v, __half& b, __half& s) {
    b = __float2half_rn(v);
    s = __float2half_rn(v - __half2float(b));
}

// ---------------- small utility kernels ----------------
__global__ void k_zero() {
    int i = blockIdx.x * blockDim.x + threadIdx.x;
    if (i < CIN) { g_sum[i] = 0.f; g_sumsq[i] = 0.f; }
    if (i < NN)  { g_cnt[i] = 0; }
}

__global__ void k_detect(const int* __restrict__ e) {
    if (threadIdx.x == 0 && blockIdx.x == 0) {
        int is64 = 1;
        for (int i = 0; i < 64; ++i)
            if (e[2 * i + 1] != 0) { is64 = 0; break; }
        g_is64 = is64;
    }
}

__global__ void k_convert(const void* __restrict__ edges) {
    int i = blockIdx.x * blockDim.x + threadIdx.x;
    if (i >= EE) return;
    int s, d;
    if (g_is64) {
        const long long* e = (const long long*)edges;
        s = (int)e[i];  d = (int)e[EE + i];
    } else {
        const int* e = (const int*)edges;
        s = e[i];  d = e[EE + i];
    }
    g_srcs[i] = s;  g_dsts[i] = d;
}

__global__ void k_count() {
    int i = blockIdx.x * blockDim.x + threadIdx.x;
    if (i >= EE) return;
    atomicAdd(&g_cnt[g_dsts[i]], 1);
}

__global__ void k_dinv() {
    int i = blockIdx.x * blockDim.x + threadIdx.x;
    if (i >= NN) return;
    g_dinv[i] = rsqrtf((float)(g_cnt[i] + 1));
}

__global__ void k_scan() {
    __shared__ int sh[1024];
    const int t = threadIdx.x;
    int run = 0;
    for (int base = 0; base < NN; base += 1024) {
        int idx = base + t;
        int v = (idx < NN) ? g_cnt[idx] : 0;
        sh[t] = v;
        __syncthreads();
        for (int off = 1; off < 1024; off <<= 1) {
            int add = (t >= off) ? sh[t - off] : 0;
            __syncthreads();
            sh[t] += add;
            __syncthreads();
        }
        if (idx < NN) {
            int ex = run + sh[t] - v;
            g_rowptr[idx] = ex;
            g_cur[idx]    = ex;
        }
        int tot = sh[1023];
        __syncthreads();
        run += tot;
    }
    if (t == 0) g_rowptr[NN] = run;
}

__global__ void k_fill() {
    int i = blockIdx.x * blockDim.x + threadIdx.x;
    if (i >= EE) return;
    int d = g_dsts[i];
    int s = g_srcs[i];
    int pos = atomicAdd(&g_cur[d], 1);
    g_cols[pos] = s;
    g_wt[pos]   = g_dinv[s] * g_dinv[d];
}

__global__ void k_stats(const float* __restrict__ x) {
    const int t = threadIdx.x;
    float s0 = 0.f, s1 = 0.f, s2 = 0.f, s3 = 0.f;
    float q0 = 0.f, q1 = 0.f, q2 = 0.f, q3 = 0.f;
    for (int r = blockIdx.x; r < NN; r += gridDim.x) {
        const float* row = x + (size_t)r * CIN;
        float v0 = row[t];       s0 += v0; q0 += v0 * v0;
        float v1 = row[t + 256]; s1 += v1; q1 += v1 * v1;
        float v2 = row[t + 512]; s2 += v2; q2 += v2 * v2;
        float v3 = row[t + 768]; s3 += v3; q3 += v3 * v3;
    }
    atomicAdd(&g_sum[t],       s0); atomicAdd(&g_sumsq[t],       q0);
    atomicAdd(&g_sum[t + 256], s1); atomicAdd(&g_sumsq[t + 256], q1);
    atomicAdd(&g_sum[t + 512], s2); atomicAdd(&g_sumsq[t + 512], q2);
    atomicAdd(&g_sum[t + 768], s3); atomicAdd(&g_sumsq[t + 768], q3);
}

__global__ void k_fin(const float* __restrict__ gw,
                      const float* __restrict__ gb,
                      const float* __restrict__ gms) {
    int i = blockIdx.x * blockDim.x + threadIdx.x;
    if (i >= CIN) return;
    float mean = g_sum[i]   * (1.0f / NN);
    float ex2  = g_sumsq[i] * (1.0f / NN);
    float s    = gms[i];
    float var  = ex2 - 2.f * s * mean * mean + s * s * mean * mean;
    float rstd = rsqrtf(var + GN_EPS);
    float al   = rstd * gw[i];
    g_alpha[i] = al;
    g_beta[i]  = gb[i] - s * mean * al;
}

// Build A1'' = hsplit(affine(x)) : [M][2048] = [big | small]
__global__ void k_build_a1(const float* __restrict__ x) {
    int i = blockIdx.x * blockDim.x + threadIdx.x;
    if (i >= NN * CIN) return;
    int m = i >> 10, k = i & 1023;
    float v = fmaf(x[i], g_alpha[k], g_beta[k]);
    __half b, s;
    hsplit(v, b, s);
    size_t base = (size_t)m * KEXP;
    g_a1h[base + k]      = b;
    g_a1h[base + KH + k] = s;
}

// Build B big planes: g_b1h[k][n] = fp16(W1); g_b2h[k][n] = fp16([Wm|Ws])
__global__ void k_build_w(const float* __restrict__ W1,
                          const float* __restrict__ Wm,
                          const float* __restrict__ Ws) {
    int i = blockIdx.x * blockDim.x + threadIdx.x;
    if (i >= CIN * HID) return;
    int k = i >> 10, n = i & 1023;
    g_b1h[i] = __float2half_rn(W1[i]);
    float w = (n < COUT) ? Wm[(size_t)k * COUT + n] : Ws[(size_t)k * COUT + n - COUT];
    g_b2h[i] = __float2half_rn(w);
}

// ---------------- fp16 tensor-core GEMM ----------------
// CTA 128x128, 4 warps (64x64 warp tiles), BK=32, 3-stage cp.async ring.
// Per stage: two A planes (big, small) x one shared B tile -> acc (fp32).
// MODE 0: g_buf1 = A1'' @ B1            MODE 1: out = A2'' @ B2 + bias
template <int MODE>
__global__ void __launch_bounds__(128, 2)
k_mma(const float* __restrict__ bias0, const float* __restrict__ bias1,
      float* __restrict__ Cout)
{
    extern __shared__ __half smh[];
    const __half* __restrict__ A = (MODE == 0) ? g_a1h : g_a2h;
    const __half* __restrict__ B = (MODE == 0) ? g_b1h : g_b2h;

    constexpr int STA = 128 * 40;            // one A plane tile (halfs), pad 32->40
    constexpr int STB = 32 * 136;            // B tile, pad 128->136
    constexpr int STG = 2 * STA + STB;       // 14592 halfs / stage

    const int tid  = threadIdx.x;
    const int warp = tid >> 5;
    const int lane = tid & 31;
    const int bm0  = blockIdx.y * 128;
    const int bn0  = blockIdx.x * 128;

    const __half* aR = A + (size_t)(bm0 + tid) * KEXP;
    const int brow = tid >> 2, bq = tid & 3;
    const __half* bR = B + (size_t)brow * HID + bn0;

    #define LOAD_STAGE(s) do {                                               \
        __half* st_ = smh + ((s) % 3) * STG;                                 \
        const __half* a0_ = aR + (s) * 32;                                   \
        _Pragma("unroll")                                                    \
        for (int c = 0; c < 4; ++c) {                                        \
            cpa16s(smem_u32(st_ + tid * 40 + c * 8),        a0_ + c * 8);    \
            cpa16s(smem_u32(st_ + STA + tid * 40 + c * 8),  a0_ + KH + c * 8); \
        }                                                                    \
        const __half* b_ = bR + (size_t)(s) * 32 * HID;                      \
        _Pragma("unroll")                                                    \
        for (int j = 0; j < 4; ++j) {                                        \
            int ch = bq + 4 * j;                                             \
            cpa16s(smem_u32(st_ + 2 * STA + brow * 136 + ch * 8), b_ + ch * 8); \
        }                                                                    \
        asm volatile("cp.async.commit_group;" ::: "memory");                 \
    } while (0)

    const int mbase = (warp >> 1) * 64;
    const int nbase = (warp & 1) * 64;
    const int lrow  = lane & 15;
    const int lcol  = (lane >> 4) << 3;

    float acc[4][8][4];
    #pragma unroll
    for (int a = 0; a < 4; ++a)
        #pragma unroll
        for (int b = 0; b < 8; ++b)
            #pragma unroll
            for (int c = 0; c < 4; ++c) acc[a][b][c] = 0.f;

    LOAD_STAGE(0);
    LOAD_STAGE(1);

    constexpr int NIT = KH / 32;   // 32
    #pragma unroll 1
    for (int s = 0; s < NIT; ++s) {
        if (s + 1 < NIT) asm volatile("cp.async.wait_group 1;" ::: "memory");
        else             asm volatile("cp.async.wait_group 0;" ::: "memory");
        __syncthreads();

        const __half* st = smh + (s % 3) * STG;
        #pragma unroll
        for (int ks = 0; ks < 32; ks += 16) {
            unsigned bf[8][2];
            #pragma unroll
            for (int ntp = 0; ntp < 4; ++ntp) {
                unsigned t4[4];
                ldsm4t(t4, st + 2 * STA + (ks + lrow) * 136 + nbase + ntp * 16 + lcol);
                bf[ntp * 2][0]     = t4[0];  bf[ntp * 2][1]     = t4[1];
                bf[ntp * 2 + 1][0] = t4[2];  bf[ntp * 2 + 1][1] = t4[3];
            }
            #pragma unroll
            for (int pl = 0; pl < 2; ++pl) {
                unsigned af[4][4];
                const __half* ab = st + pl * STA;
                #pragma unroll
                for (int mt = 0; mt < 4; ++mt)
                    ldsm4(af[mt], ab + (mbase + mt * 16 + lrow) * 40 + ks + lcol);
                #pragma unroll
                for (int mt = 0; mt < 4; ++mt)
                    #pragma unroll
                    for (int nt = 0; nt < 8; ++nt)
                        mma16816h(acc[mt][nt], af[mt], bf[nt]);
            }
        }
        if (s + 2 < NIT) LOAD_STAGE(s + 2);
    }

    // ---- epilogue ----
    const int g  = lane >> 2;
    const int tg = lane & 3;
    #pragma unroll
    for (int mt = 0; mt < 4; ++mt) {
        #pragma unroll
        for (int nt = 0; nt < 8; ++nt) {
            int r0 = bm0 + mbase + mt * 16 + g;
            int r1 = r0 + 8;
            int c  = bn0 + nbase + nt * 8 + tg * 2;
            float* a4 = acc[mt][nt];
            if (MODE == 0) {
                if (r0 < NN) *(float2*)&g_buf1[(size_t)r0 * HID + c] = make_float2(a4[0], a4[1]);
                if (r1 < NN) *(float2*)&g_buf1[(size_t)r1 * HID + c] = make_float2(a4[2], a4[3]);
            } else {
                if (c < COUT) {
                    float2 v0 = make_float2(a4[0] + bias0[c], a4[1] + bias0[c + 1]);
                    float2 v1 = make_float2(a4[2] + bias0[c], a4[3] + bias0[c + 1]);
                    if (r0 < NN) {
                        *(float2*)&Cout[(size_t)r0 * COUT + c] = v0;                   // z
                        *(float2*)&Cout[(size_t)(NN + r0) * COUT + c] = v0;            // mu
                    }
                    if (r1 < NN) {
                        *(float2*)&Cout[(size_t)r1 * COUT + c] = v1;
                        *(float2*)&Cout[(size_t)(NN + r1) * COUT + c] = v1;
                    }
                } else {
                    int cs = c - COUT;
                    float2 v0 = make_float2(a4[0] + bias1[cs], a4[1] + bias1[cs + 1]);
                    float2 v1 = make_float2(a4[2] + bias1[cs], a4[3] + bias1[cs + 1]);
                    if (r0 < NN) *(float2*)&Cout[(size_t)(2 * NN + r0) * COUT + cs] = v0;  // logstd
                    if (r1 < NN) *(float2*)&Cout[(size_t)(2 * NN + r1) * COUT + cs] = v1;
                }
            }
        }
    }
    #undef LOAD_STAGE
}

// ---------------- aggregation ----------------
// agg1: g_buf2 = leakyrelu(A_norm @ g_buf1 + b1)   (f32 out)
__global__ void __launch_bounds__(256)
k_agg1(const float* __restrict__ bias) {
    const int i = blockIdx.x;
    const int t = threadIdx.x;
    const float dv = g_dinv[i];
    const float sw = dv * dv;

    const float* selfrow = g_buf1 + (size_t)i * HID;
    float a0 = sw * selfrow[t];
    float a1 = sw * selfrow[t + 256];
    float a2 = sw * selfrow[t + 512];
    float a3 = sw * selfrow[t + 768];

    const int beg = g_rowptr[i];
    const int end = g_rowptr[i + 1];
    #pragma unroll 2
    for (int e = beg; e < end; ++e) {
        const int   s = g_cols[e];
        const float w = g_wt[e];
        const float* r = g_buf1 + (size_t)s * HID;
        a0 = fmaf(w, r[t],       a0);
        a1 = fmaf(w, r[t + 256], a1);
        a2 = fmaf(w, r[t + 512], a2);
        a3 = fmaf(w, r[t + 768], a3);
    }
    a0 += bias[t];       a0 = (a0 > 0.f) ? a0 : SLOPE * a0;
    a1 += bias[t + 256]; a1 = (a1 > 0.f) ? a1 : SLOPE * a1;
    a2 += bias[t + 512]; a2 = (a2 > 0.f) ? a2 : SLOPE * a2;
    a3 += bias[t + 768]; a3 = (a3 > 0.f) ? a3 : SLOPE * a3;

    float* o = g_buf2 + (size_t)i * HID;
    o[t] = a0;  o[t + 256] = a1;  o[t + 512] = a2;  o[t + 768] = a3;
}

// agg2: g_a2h = hsplit(A_norm @ g_buf2)   (fp16 2-plane, GEMM2 input)
__global__ void __launch_bounds__(256)
k_agg2() {
    const int i = blockIdx.x;
    const int t = threadIdx.x;
    const float dv = g_dinv[i];
    const float sw = dv * dv;

    const float* selfrow = g_buf2 + (size_t)i * HID;
    float a0 = sw * selfrow[t];
    float a1 = sw * selfrow[t + 256];
    float a2 = sw * selfrow[t + 512];
    float a3 = sw * selfrow[t + 768];

    const int beg = g_rowptr[i];
    const int end = g_rowptr[i + 1];
    #pragma unroll 2
    for (int e = beg; e < end; ++e) {
        const int   s = g_cols[e];
        const float w = g_wt[e];
        const float* r = g_buf2 + (size_t)s * HID;
        a0 = fmaf(w, r[t],       a0);
        a1 = fmaf(w, r[t + 256], a1);
        a2 = fmaf(w, r[t + 512], a2);
        a3 = fmaf(w, r[t + 768], a3);
    }

    __half* o = g_a2h + (size_t)i * KEXP;
    __half b, s;
    hsplit(a0, b, s); o[t]       = b; o[KH + t]       = s;
    hsplit(a1, b, s); o[t + 256] = b; o[KH + t + 256] = s;
    hsplit(a2, b, s); o[t + 512] = b; o[KH + t + 512] = s;
    hsplit(a3, b, s); o[t + 768] = b; o[KH + t + 768] = s;
}

// ---------------- launch ----------------
extern "C" void kernel_launch(void* const* d_in, const int* in_sizes, int n_in,
                              void* d_out, int out_size) {
    const float* x   = (const float*)d_in[0];
    const void*  edg = d_in[1];
    const float* W1  = (const float*)d_in[2];
    const float* b1  = (const float*)d_in[3];
    const float* Wm  = (const float*)d_in[4];
    const float* bm  = (const float*)d_in[5];
    const float* Ws  = (const float*)d_in[6];
    const float* bs  = (const float*)d_in[7];
    const float* gw  = (const float*)d_in[8];
    const float* gb  = (const float*)d_in[9];
    const float* gms = (const float*)d_in[10];
    float* out = (float*)d_out;

    constexpr int DSMEM = (2 * 128 * 40 + 32 * 136) * 3 * 2;   // 87552 bytes
    cudaFuncSetAttribute(k_mma<0>, cudaFuncAttributeMaxDynamicSharedMemorySize, DSMEM);
    cudaFuncSetAttribute(k_mma<1>, cudaFuncAttributeMaxDynamicSharedMemorySize, DSMEM);

    // graph preprocessing + norm stats
    k_zero<<<(NN + 255) / 256, 256>>>();
    k_detect<<<1, 1>>>((const int*)edg);
    k_convert<<<(EE + 255) / 256, 256>>>(edg);
    k_count<<<(EE + 255) / 256, 256>>>();
    k_dinv<<<(NN + 255) / 256, 256>>>();
    k_scan<<<1, 1024>>>();
    k_fill<<<(EE + 255) / 256, 256>>>();
    k_stats<<<200, 256>>>(x);
    k_fin<<<(CIN + 255) / 256, 256>>>(gw, gb, gms);

    // fp16-split operand construction
    k_build_a1<<<(NN * CIN + 255) / 256, 256>>>(x);
    k_build_w<<<(CIN * HID + 255) / 256, 256>>>(W1, Wm, Ws);

    // layer 1: h = graphnorm(x) @ W1
    dim3 g1(HID / 128, MPAD / 128);     // (8, 79)
    k_mma<0><<<g1, 128, DSMEM>>>(nullptr, nullptr, nullptr);

    // buf2 = leakyrelu(A_norm @ h + b1);  a2'' = hsplit(A_norm @ buf2)
    k_agg1<<<NN, 256>>>(b1);
    k_agg2<<<NN, 256>>>();

    // layer 2: out = a2'' @ [Wm|Ws] + bias   (z = mu duplicated)
    dim3 g2(HID / 128, MPAD / 128);
    k_mma<1><<<g2, 128, DSMEM>>>(bm, bs, out);
}

// round 6
// speedup vs baseline: 3.0360x; 1.2422x over previous
#include <cuda_runtime.h>
#include <cuda_fp16.h>
#include <cstdint>

#define NN   10000
#define EE   160000
#define CIN  1024
#define HID  1024
#define COUT 512
#define KH   1024
#define MPAD 10112           // 79 * 128
#define GN_EPS 1e-5f
#define SLOPE  0.1f

// ---------------- scratch (static device globals; no runtime alloc) ----------------
__device__ __half g_h1[(size_t)NN * HID];           // h = GEMM1 out (fp16)
__device__ __half g_h2[(size_t)NN * HID];           // agg1 out (fp16)
__device__ __half g_a1h[(size_t)MPAD * KH];         // GEMM1 A (fp16)
__device__ __half g_a2h[(size_t)MPAD * KH];         // GEMM2 A = agg2 out (fp16)
__device__ __half g_b1h[(size_t)KH * HID];          // GEMM1 B [k][n] = fp16(W1)
__device__ __half g_b2h[(size_t)KH * HID];          // GEMM2 B [k][n] = fp16([Wm|Ws])
__device__ float g_alpha[CIN];
__device__ float g_beta[CIN];
__device__ float g_sum[CIN];
__device__ float g_sumsq[CIN];
__device__ float g_dinv[NN];
__device__ int   g_cnt[NN];
__device__ int   g_rowptr[NN + 1];
__device__ int   g_cur[NN];
__device__ int   g_srcs[EE];
__device__ int   g_dsts[EE];
__device__ int   g_cols[EE];
__device__ float g_wt[EE];
__device__ int   g_is64;

// ---------------- PTX helpers ----------------
__device__ __forceinline__ unsigned smem_u32(const void* p) {
    return (unsigned)__cvta_generic_to_shared(p);
}
__device__ __forceinline__ void cpa16s(unsigned dst, const void* src) {
    asm volatile("cp.async.cg.shared.global [%0], [%1], 16;" :: "r"(dst), "l"(src) : "memory");
}
__device__ __forceinline__ void ldsm4(unsigned* r, const void* p) {
    unsigned a = smem_u32(p);
    asm volatile("ldmatrix.sync.aligned.m8n8.x4.shared.b16 {%0,%1,%2,%3}, [%4];"
                 : "=r"(r[0]), "=r"(r[1]), "=r"(r[2]), "=r"(r[3]) : "r"(a));
}
__device__ __forceinline__ void ldsm4t(unsigned* r, const void* p) {
    unsigned a = smem_u32(p);
    asm volatile("ldmatrix.sync.aligned.m8n8.x4.trans.shared.b16 {%0,%1,%2,%3}, [%4];"
                 : "=r"(r[0]), "=r"(r[1]), "=r"(r[2]), "=r"(r[3]) : "r"(a));
}
__device__ __forceinline__ void mma16816h(float* d, const unsigned* a, const unsigned* b) {
    asm volatile("mma.sync.aligned.m16n8k16.row.col.f32.f16.f16.f32 "
                 "{%0,%1,%2,%3}, {%4,%5,%6,%7}, {%8,%9}, {%0,%1,%2,%3};"
                 : "+f"(d[0]), "+f"(d[1]), "+f"(d[2]), "+f"(d[3])
                 : "r"(a[0]), "r"(a[1]), "r"(a[2]), "r"(a[3]), "r"(b[0]), "r"(b[1]));
}

// ---------------- small utility kernels ----------------
__global__ void k_zero() {
    int i = blockIdx.x * blockDim.x + threadIdx.x;
    if (i < CIN) { g_sum[i] = 0.f; g_sumsq[i] = 0.f; }
    if (i < NN)  { g_cnt[i] = 0; }
}

__global__ void k_detect(const int* __restrict__ e) {
    if (threadIdx.x == 0 && blockIdx.x == 0) {
        int is64 = 1;
        for (int i = 0; i < 64; ++i)
            if (e[2 * i + 1] != 0) { is64 = 0; break; }
        g_is64 = is64;
    }
}

// convert + degree count fused
__global__ void k_convert(const void* __restrict__ edges) {
    int i = blockIdx.x * blockDim.x + threadIdx.x;
    if (i >= EE) return;
    int s, d;
    if (g_is64) {
        const long long* e = (const long long*)edges;
        s = (int)e[i];  d = (int)e[EE + i];
    } else {
        const int* e = (const int*)edges;
        s = e[i];  d = e[EE + i];
    }
    g_srcs[i] = s;  g_dsts[i] = d;
    atomicAdd(&g_cnt[d], 1);
}

__global__ void k_dinv() {
    int i = blockIdx.x * blockDim.x + threadIdx.x;
    if (i >= NN) return;
    g_dinv[i] = rsqrtf((float)(g_cnt[i] + 1));   // +1 self loop
}

__global__ void k_scan() {
    __shared__ int sh[1024];
    const int t = threadIdx.x;
    int run = 0;
    for (int base = 0; base < NN; base += 1024) {
        int idx = base + t;
        int v = (idx < NN) ? g_cnt[idx] : 0;
        sh[t] = v;
        __syncthreads();
        for (int off = 1; off < 1024; off <<= 1) {
            int add = (t >= off) ? sh[t - off] : 0;
            __syncthreads();
            sh[t] += add;
            __syncthreads();
        }
        if (idx < NN) {
            int ex = run + sh[t] - v;
            g_rowptr[idx] = ex;
            g_cur[idx]    = ex;
        }
        int tot = sh[1023];
        __syncthreads();
        run += tot;
    }
    if (t == 0) g_rowptr[NN] = run;
}

__global__ void k_fill() {
    int i = blockIdx.x * blockDim.x + threadIdx.x;
    if (i >= EE) return;
    int d = g_dsts[i];
    int s = g_srcs[i];
    int pos = atomicAdd(&g_cur[d], 1);
    g_cols[pos] = s;
    g_wt[pos]   = g_dinv[s] * g_dinv[d];
}

__global__ void k_stats(const float* __restrict__ x) {
    const int t = threadIdx.x;
    float s0 = 0.f, s1 = 0.f, s2 = 0.f, s3 = 0.f;
    float q0 = 0.f, q1 = 0.f, q2 = 0.f, q3 = 0.f;
    for (int r = blockIdx.x; r < NN; r += gridDim.x) {
        const float* row = x + (size_t)r * CIN;
        float v0 = row[t];       s0 += v0; q0 += v0 * v0;
        float v1 = row[t + 256]; s1 += v1; q1 += v1 * v1;
        float v2 = row[t + 512]; s2 += v2; q2 += v2 * v2;
        float v3 = row[t + 768]; s3 += v3; q3 += v3 * v3;
    }
    atomicAdd(&g_sum[t],       s0); atomicAdd(&g_sumsq[t],       q0);
    atomicAdd(&g_sum[t + 256], s1); atomicAdd(&g_sumsq[t + 256], q1);
    atomicAdd(&g_sum[t + 512], s2); atomicAdd(&g_sumsq[t + 512], q2);
    atomicAdd(&g_sum[t + 768], s3); atomicAdd(&g_sumsq[t + 768], q3);
}

__global__ void k_fin(const float* __restrict__ gw,
                      const float* __restrict__ gb,
                      const float* __restrict__ gms) {
    int i = blockIdx.x * blockDim.x + threadIdx.x;
    if (i >= CIN) return;
    float mean = g_sum[i]   * (1.0f / NN);
    float ex2  = g_sumsq[i] * (1.0f / NN);
    float s    = gms[i];
    float var  = ex2 - 2.f * s * mean * mean + s * s * mean * mean;
    float rstd = rsqrtf(var + GN_EPS);
    float al   = rstd * gw[i];
    g_alpha[i] = al;
    g_beta[i]  = gb[i] - s * mean * al;
}

// A1 = fp16(affine(x))
__global__ void k_build_a1(const float* __restrict__ x) {
    int i = blockIdx.x * blockDim.x + threadIdx.x;
    if (i >= NN * CIN) return;
    int m = i >> 10, k = i & 1023;
    float v = fmaf(x[i], g_alpha[k], g_beta[k]);
    g_a1h[(size_t)m * KH + k] = __float2half_rn(v);
}

// B planes: g_b1h[k][n] = fp16(W1); g_b2h[k][n] = fp16([Wm|Ws])
__global__ void k_build_w(const float* __restrict__ W1,
                          const float* __restrict__ Wm,
                          const float* __restrict__ Ws) {
    int i = blockIdx.x * blockDim.x + threadIdx.x;
    if (i >= CIN * HID) return;
    int k = i >> 10, n = i & 1023;
    g_b1h[i] = __float2half_rn(W1[i]);
    float w = (n < COUT) ? Wm[(size_t)k * COUT + n] : Ws[(size_t)k * COUT + n - COUT];
    g_b2h[i] = __float2half_rn(w);
}

// ---------------- fp16 tensor-core GEMM ----------------
// CTA 128x128, 4 warps (64x64 warp tiles), BK=64, 3-stage cp.async ring, K=1024.
// MODE 0: g_h1 (fp16) = A1 @ B1        MODE 1: out (f32) = A2 @ B2 + bias
template <int MODE>
__global__ void __launch_bounds__(128, 2)
k_mma(const float* __restrict__ bias0, const float* __restrict__ bias1,
      float* __restrict__ Cout)
{
    extern __shared__ __half smh[];
    const __half* __restrict__ A = (MODE == 0) ? g_a1h : g_a2h;
    const __half* __restrict__ B = (MODE == 0) ? g_b1h : g_b2h;

    constexpr int STA = 128 * 72;            // A tile 128x64, pad 64->72
    constexpr int STB = 64 * 136;            // B tile 64x128, pad 128->136
    constexpr int STG = STA + STB;           // 17920 halfs / stage

    const int tid  = threadIdx.x;
    const int warp = tid >> 5;
    const int lane = tid & 31;
    const int bm0  = blockIdx.y * 128;
    const int bn0  = blockIdx.x * 128;

    const __half* aR = A + (size_t)(bm0 + tid) * KH;
    const int brow = tid >> 1, bh = tid & 1;
    const __half* bR = B + (size_t)brow * HID + bn0;

    #define LOAD_STAGE(s) do {                                                \
        __half* st_ = smh + ((s) % 3) * STG;                                  \
        const __half* a_ = aR + (s) * 64;                                     \
        _Pragma("unroll")                                                     \
        for (int c = 0; c < 8; ++c)                                           \
            cpa16s(smem_u32(st_ + tid * 72 + c * 8), a_ + c * 8);             \
        const __half* b_ = bR + (size_t)(s) * 64 * HID;                       \
        _Pragma("unroll")                                                     \
        for (int j = 0; j < 8; ++j) {                                         \
            int ch = bh * 8 + j;                                              \
            cpa16s(smem_u32(st_ + STA + brow * 136 + ch * 8), b_ + ch * 8);   \
        }                                                                     \
        asm volatile("cp.async.commit_group;" ::: "memory");                  \
    } while (0)

    const int mbase = (warp >> 1) * 64;
    const int nbase = (warp & 1) * 64;
    const int lrow  = lane & 15;
    const int lcol  = (lane >> 4) << 3;

    float acc[4][8][4];
    #pragma unroll
    for (int a = 0; a < 4; ++a)
        #pragma unroll
        for (int b = 0; b < 8; ++b)
            #pragma unroll
            for (int c = 0; c < 4; ++c) acc[a][b][c] = 0.f;

    LOAD_STAGE(0);
    LOAD_STAGE(1);

    constexpr int NIT = KH / 64;   // 16
    #pragma unroll 1
    for (int s = 0; s < NIT; ++s) {
        if (s + 1 < NIT) asm volatile("cp.async.wait_group 1;" ::: "memory");
        else             asm volatile("cp.async.wait_group 0;" ::: "memory");
        __syncthreads();

        const __half* st = smh + (s % 3) * STG;
        #pragma unroll
        for (int ks = 0; ks < 64; ks += 16) {
            unsigned bf[8][2];
            #pragma unroll
            for (int ntp = 0; ntp < 4; ++ntp) {
                unsigned t4[4];
                ldsm4t(t4, st + STA + (ks + lrow) * 136 + nbase + ntp * 16 + lcol);
                bf[ntp * 2][0]     = t4[0];  bf[ntp * 2][1]     = t4[1];
                bf[ntp * 2 + 1][0] = t4[2];  bf[ntp * 2 + 1][1] = t4[3];
            }
            unsigned af[4][4];
            #pragma unroll
            for (int mt = 0; mt < 4; ++mt)
                ldsm4(af[mt], st + (mbase + mt * 16 + lrow) * 72 + ks + lcol);
            #pragma unroll
            for (int mt = 0; mt < 4; ++mt)
                #pragma unroll
                for (int nt = 0; nt < 8; ++nt)
                    mma16816h(acc[mt][nt], af[mt], bf[nt]);
        }
        if (s + 2 < NIT) LOAD_STAGE(s + 2);
    }

    // ---- epilogue ----
    const int g  = lane >> 2;
    const int tg = lane & 3;
    #pragma unroll
    for (int mt = 0; mt < 4; ++mt) {
        #pragma unroll
        for (int nt = 0; nt < 8; ++nt) {
            int r0 = bm0 + mbase + mt * 16 + g;
            int r1 = r0 + 8;
            int c  = bn0 + nbase + nt * 8 + tg * 2;
            float* a4 = acc[mt][nt];
            if (MODE == 0) {
                __half2 v0 = __floats2half2_rn(a4[0], a4[1]);
                __half2 v1 = __floats2half2_rn(a4[2], a4[3]);
                if (r0 < NN) *(__half2*)&g_h1[(size_t)r0 * HID + c] = v0;
                if (r1 < NN) *(__half2*)&g_h1[(size_t)r1 * HID + c] = v1;
            } else {
                if (c < COUT) {
                    float2 v0 = make_float2(a4[0] + bias0[c], a4[1] + bias0[c + 1]);
                    float2 v1 = make_float2(a4[2] + bias0[c], a4[3] + bias0[c + 1]);
                    if (r0 < NN) {
                        *(float2*)&Cout[(size_t)r0 * COUT + c] = v0;                   // z
                        *(float2*)&Cout[(size_t)(NN + r0) * COUT + c] = v0;            // mu
                    }
                    if (r1 < NN) {
                        *(float2*)&Cout[(size_t)r1 * COUT + c] = v1;
                        *(float2*)&Cout[(size_t)(NN + r1) * COUT + c] = v1;
                    }
                } else {
                    int cs = c - COUT;
                    float2 v0 = make_float2(a4[0] + bias1[cs], a4[1] + bias1[cs + 1]);
                    float2 v1 = make_float2(a4[2] + bias1[cs], a4[3] + bias1[cs + 1]);
                    if (r0 < NN) *(float2*)&Cout[(size_t)(2 * NN + r0) * COUT + cs] = v0;  // logstd
                    if (r1 < NN) *(float2*)&Cout[(size_t)(2 * NN + r1) * COUT + cs] = v1;
                }
            }
        }
    }
    #undef LOAD_STAGE
}

// ---------------- aggregation (fp16 gather, f32 accumulate) ----------------
// agg1: g_h2 = fp16(leakyrelu(A_norm @ g_h1 + b1))
__global__ void __launch_bounds__(256)
k_agg1(const float* __restrict__ bias) {
    const int i = blockIdx.x;
    const int t = threadIdx.x;
    const float dv = g_dinv[i];
    const float sw = dv * dv;

    const __half2* self = (const __half2*)(g_h1 + (size_t)i * HID);
    float2 f0 = __half22float2(self[t]);
    float2 f1 = __half22float2(self[t + 256]);
    float a0 = sw * f0.x, a1 = sw * f0.y, a2 = sw * f1.x, a3 = sw * f1.y;

    const int beg = g_rowptr[i];
    const int end = g_rowptr[i + 1];
    #pragma unroll 2
    for (int e = beg; e < end; ++e) {
        const int   s = g_cols[e];
        const float w = g_wt[e];
        const __half2* r = (const __half2*)(g_h1 + (size_t)s * HID);
        float2 r0 = __half22float2(r[t]);
        float2 r1 = __half22float2(r[t + 256]);
        a0 = fmaf(w, r0.x, a0);
        a1 = fmaf(w, r0.y, a1);
        a2 = fmaf(w, r1.x, a2);
        a3 = fmaf(w, r1.y, a3);
    }
    a0 += bias[2 * t];       a0 = (a0 > 0.f) ? a0 : SLOPE * a0;
    a1 += bias[2 * t + 1];   a1 = (a1 > 0.f) ? a1 : SLOPE * a1;
    a2 += bias[2 * t + 512]; a2 = (a2 > 0.f) ? a2 : SLOPE * a2;
    a3 += bias[2 * t + 513]; a3 = (a3 > 0.f) ? a3 : SLOPE * a3;

    __half2* o = (__half2*)(g_h2 + (size_t)i * HID);
    o[t]       = __floats2half2_rn(a0, a1);
    o[t + 256] = __floats2half2_rn(a2, a3);
}

// agg2: g_a2h = fp16(A_norm @ g_h2)   (GEMM2 A input)
__global__ void __launch_bounds__(256)
k_agg2() {
    const int i = blockIdx.x;
    const int t = threadIdx.x;
    const float dv = g_dinv[i];
    const float sw = dv * dv;

    const __half2* self = (const __half2*)(g_h2 + (size_t)i * HID);
    float2 f0 = __half22float2(self[t]);
    float2 f1 = __half22float2(self[t + 256]);
    float a0 = sw * f0.x, a1 = sw * f0.y, a2 = sw * f1.x, a3 = sw * f1.y;

    const int beg = g_rowptr[i];
    const int end = g_rowptr[i + 1];
    #pragma unroll 2
    for (int e = beg; e < end; ++e) {
        const int   s = g_cols[e];
        const float w = g_wt[e];
        const __half2* r = (const __half2*)(g_h2 + (size_t)s * HID);
        float2 r0 = __half22float2(r[t]);
        float2 r1 = __half22float2(r[t + 256]);
        a0 = fmaf(w, r0.x, a0);
        a1 = fmaf(w, r0.y, a1);
        a2 = fmaf(w, r1.x, a2);
        a3 = fmaf(w, r1.y, a3);
    }

    __half2* o = (__half2*)(g_a2h + (size_t)i * KH);
    o[t]       = __floats2half2_rn(a0, a1);
    o[t + 256] = __floats2half2_rn(a2, a3);
}

// ---------------- launch ----------------
extern "C" void kernel_launch(void* const* d_in, const int* in_sizes, int n_in,
                              void* d_out, int out_size) {
    const float* x   = (const float*)d_in[0];
    const void*  edg = d_in[1];
    const float* W1  = (const float*)d_in[2];
    const float* b1  = (const float*)d_in[3];
    const float* Wm  = (const float*)d_in[4];
    const float* bm  = (const float*)d_in[5];
    const float* Ws  = (const float*)d_in[6];
    const float* bs  = (const float*)d_in[7];
    const float* gw  = (const float*)d_in[8];
    const float* gb  = (const float*)d_in[9];
    const float* gms = (const float*)d_in[10];
    float* out = (float*)d_out;

    constexpr int DSMEM = (128 * 72 + 64 * 136) * 3 * 2;   // 107520 bytes
    cudaFuncSetAttribute(k_mma<0>, cudaFuncAttributeMaxDynamicSharedMemorySize, DSMEM);
    cudaFuncSetAttribute(k_mma<1>, cudaFuncAttributeMaxDynamicSharedMemorySize, DSMEM);

    // graph preprocessing + norm stats
    k_zero<<<(NN + 255) / 256, 256>>>();
    k_detect<<<1, 1>>>((const int*)edg);
    k_convert<<<(EE + 255) / 256, 256>>>(edg);
    k_dinv<<<(NN + 255) / 256, 256>>>();
    k_scan<<<1, 1024>>>();
    k_fill<<<(EE + 255) / 256, 256>>>();
    k_stats<<<200, 256>>>(x);
    k_fin<<<(CIN + 255) / 256, 256>>>(gw, gb, gms);

    // fp16 operand construction
    k_build_a1<<<(NN * CIN + 255) / 256, 256>>>(x);
    k_build_w<<<(CIN * HID + 255) / 256, 256>>>(W1, Wm, Ws);

    // layer 1: h = graphnorm(x) @ W1   (fp16 out)
    dim3 g1(HID / 128, MPAD / 128);     // (8, 79)
    k_mma<0><<<g1, 128, DSMEM>>>(nullptr, nullptr, nullptr);

    // h2 = leakyrelu(A_norm @ h + b1);  A2 = A_norm @ h2
    k_agg1<<<NN, 256>>>(b1);
    k_agg2<<<NN, 256>>>();

    // layer 2: out = A2 @ [Wm|Ws] + bias   (z = mu duplicated)
    dim3 g2(HID / 128, MPAD / 128);
    k_mma<1><<<g2, 128, DSMEM>>>(bm, bs, out);
}

// round 8
// speedup vs baseline: 4.0798x; 1.3438x over previous
#include <cuda_runtime.h>
#include <cuda_fp16.h>
#include <cstdint>

#define NN   10000
#define EE   160000
#define CIN  1024
#define HID  1024
#define COUT 512
#define KH   1024
#define MPAD 10112           // padded row allocation (>= 105*96 = 10080)
#define MT   96              // CTA M tile
#define MTILES 105           // ceil(10000/96)
#define GN_EPS 1e-5f
#define SLOPE  0.1f

// ---------------- scratch (static device globals; no runtime alloc) ----------------
__device__ __half g_h1[(size_t)NN * HID];           // h = GEMM1 out (fp16)
__device__ __half g_h2[(size_t)NN * HID];           // agg1 out (fp16)
__device__ __half g_a1h[(size_t)MPAD * KH];         // GEMM1 A (fp16)
__device__ __half g_a2h[(size_t)MPAD * KH];         // GEMM2 A = agg2 out (fp16)
__device__ __half g_b1h[(size_t)KH * HID];          // GEMM1 B [k][n] = fp16(W1)
__device__ __half g_b2h[(size_t)KH * HID];          // GEMM2 B [k][n] = fp16([Wm|Ws])
__device__ float g_alpha[CIN];
__device__ float g_beta[CIN];
__device__ float g_sum[CIN];
__device__ float g_sumsq[CIN];
__device__ float g_dinv[NN];
__device__ int   g_cnt[NN];
__device__ int   g_rowptr[NN + 1];
__device__ int   g_cur[NN];
__device__ int   g_srcs[EE];
__device__ int   g_dsts[EE];
__device__ int   g_cols[EE];
__device__ float g_wt[EE];
__device__ int   g_is64;

// ---------------- PTX helpers ----------------
__device__ __forceinline__ unsigned smem_u32(const void* p) {
    return (unsigned)__cvta_generic_to_shared(p);
}
__device__ __forceinline__ void cpa16s(unsigned dst, const void* src) {
    asm volatile("cp.async.cg.shared.global [%0], [%1], 16;" :: "r"(dst), "l"(src) : "memory");
}
__device__ __forceinline__ void ldsm4(unsigned* r, const void* p) {
    unsigned a = smem_u32(p);
    asm volatile("ldmatrix.sync.aligned.m8n8.x4.shared.b16 {%0,%1,%2,%3}, [%4];"
                 : "=r"(r[0]), "=r"(r[1]), "=r"(r[2]), "=r"(r[3]) : "r"(a));
}
__device__ __forceinline__ void ldsm4t(unsigned* r, const void* p) {
    unsigned a = smem_u32(p);
    asm volatile("ldmatrix.sync.aligned.m8n8.x4.trans.shared.b16 {%0,%1,%2,%3}, [%4];"
                 : "=r"(r[0]), "=r"(r[1]), "=r"(r[2]), "=r"(r[3]) : "r"(a));
}
__device__ __forceinline__ void mma16816h(float* d, const unsigned* a, const unsigned* b) {
    asm volatile("mma.sync.aligned.m16n8k16.row.col.f32.f16.f16.f32 "
                 "{%0,%1,%2,%3}, {%4,%5,%6,%7}, {%8,%9}, {%0,%1,%2,%3};"
                 : "+f"(d[0]), "+f"(d[1]), "+f"(d[2]), "+f"(d[3])
                 : "r"(a[0]), "r"(a[1]), "r"(a[2]), "r"(a[3]), "r"(b[0]), "r"(b[1]));
}

// ---------------- small utility kernels ----------------
// zero counters + edge dtype detection fused
__global__ void k_zero(const int* __restrict__ e) {
    int i = blockIdx.x * blockDim.x + threadIdx.x;
    if (i < CIN) { g_sum[i] = 0.f; g_sumsq[i] = 0.f; }
    if (i < NN)  { g_cnt[i] = 0; }
    if (i == 0) {
        int is64 = 1;
        for (int j = 0; j < 64; ++j)
            if (e[2 * j + 1] != 0) { is64 = 0; break; }
        g_is64 = is64;
    }
}

// convert + degree count fused
__global__ void k_convert(const void* __restrict__ edges) {
    int i = blockIdx.x * blockDim.x + threadIdx.x;
    if (i >= EE) return;
    int s, d;
    if (g_is64) {
        const long long* e = (const long long*)edges;
        s = (int)e[i];  d = (int)e[EE + i];
    } else {
        const int* e = (const int*)edges;
        s = e[i];  d = e[EE + i];
    }
    g_srcs[i] = s;  g_dsts[i] = d;
    atomicAdd(&g_cnt[d], 1);
}

// exclusive scan of g_cnt -> rowptr/cur, plus dinv (fused)
__global__ void k_scan() {
    __shared__ int sh[1024];
    const int t = threadIdx.x;
    int run = 0;
    for (int base = 0; base < NN; base += 1024) {
        int idx = base + t;
        int v = (idx < NN) ? g_cnt[idx] : 0;
        sh[t] = v;
        __syncthreads();
        for (int off = 1; off < 1024; off <<= 1) {
            int add = (t >= off) ? sh[t - off] : 0;
            __syncthreads();
            sh[t] += add;
            __syncthreads();
        }
        if (idx < NN) {
            int ex = run + sh[t] - v;
            g_rowptr[idx] = ex;
            g_cur[idx]    = ex;
            g_dinv[idx]   = rsqrtf((float)(v + 1));   // +1 self loop
        }
        int tot = sh[1023];
        __syncthreads();
        run += tot;
    }
    if (t == 0) g_rowptr[NN] = run;
}

__global__ void k_fill() {
    int i = blockIdx.x * blockDim.x + threadIdx.x;
    if (i >= EE) return;
    int d = g_dsts[i];
    int s = g_srcs[i];
    int pos = atomicAdd(&g_cur[d], 1);
    g_cols[pos] = s;
    g_wt[pos]   = g_dinv[s] * g_dinv[d];
}

__global__ void k_stats(const float* __restrict__ x) {
    const int t = threadIdx.x;
    float s0 = 0.f, s1 = 0.f, s2 = 0.f, s3 = 0.f;
    float q0 = 0.f, q1 = 0.f, q2 = 0.f, q3 = 0.f;
    for (int r = blockIdx.x; r < NN; r += gridDim.x) {
        const float* row = x + (size_t)r * CIN;
        float v0 = row[t];       s0 += v0; q0 += v0 * v0;
        float v1 = row[t + 256]; s1 += v1; q1 += v1 * v1;
        float v2 = row[t + 512]; s2 += v2; q2 += v2 * v2;
        float v3 = row[t + 768]; s3 += v3; q3 += v3 * v3;
    }
    atomicAdd(&g_sum[t],       s0); atomicAdd(&g_sumsq[t],       q0);
    atomicAdd(&g_sum[t + 256], s1); atomicAdd(&g_sumsq[t + 256], q1);
    atomicAdd(&g_sum[t + 512], s2); atomicAdd(&g_sumsq[t + 512], q2);
    atomicAdd(&g_sum[t + 768], s3); atomicAdd(&g_sumsq[t + 768], q3);
}

__global__ void k_fin(const float* __restrict__ gw,
                      const float* __restrict__ gb,
                      const float* __restrict__ gms) {
    int i = blockIdx.x * blockDim.x + threadIdx.x;
    if (i >= CIN) return;
    float mean = g_sum[i]   * (1.0f / NN);
    float ex2  = g_sumsq[i] * (1.0f / NN);
    float s    = gms[i];
    float var  = ex2 - 2.f * s * mean * mean + s * s * mean * mean;
    float rstd = rsqrtf(var + GN_EPS);
    float al   = rstd * gw[i];
    g_alpha[i] = al;
    g_beta[i]  = gb[i] - s * mean * al;
}

// A1 = fp16(affine(x))
__global__ void k_build_a1(const float* __restrict__ x) {
    int i = blockIdx.x * blockDim.x + threadIdx.x;
    if (i >= NN * CIN) return;
    int m = i >> 10, k = i & 1023;
    float v = fmaf(x[i], g_alpha[k], g_beta[k]);
    g_a1h[(size_t)m * KH + k] = __float2half_rn(v);
}

// B planes: g_b1h[k][n] = fp16(W1); g_b2h[k][n] = fp16([Wm|Ws])
__global__ void k_build_w(const float* __restrict__ W1,
                          const float* __restrict__ Wm,
                          const float* __restrict__ Ws) {
    int i = blockIdx.x * blockDim.x + threadIdx.x;
    if (i >= CIN * HID) return;
    int k = i >> 10, n = i & 1023;
    g_b1h[i] = __float2half_rn(W1[i]);
    float w = (n < COUT) ? Wm[(size_t)k * COUT + n] : Ws[(size_t)k * COUT + n - COUT];
    g_b2h[i] = __float2half_rn(w);
}

// ---------------- fp16 tensor-core GEMM ----------------
// CTA 96x128 (wave-balanced: 840 CTAs / 296 concurrent = 2.84 waves, 94.6% eff),
// 4 warps of 48x64, BK=64, 3-stage cp.async ring, K=1024.
// MODE 0: g_h1 (fp16) = A1 @ B1        MODE 1: out (f32) = A2 @ B2 + bias
template <int MODE>
__global__ void __launch_bounds__(128, 2)
k_mma(const float* __restrict__ bias0, const float* __restrict__ bias1,
      float* __restrict__ Cout)
{
    extern __shared__ __half smh[];
    const __half* __restrict__ A = (MODE == 0) ? g_a1h : g_a2h;
    const __half* __restrict__ B = (MODE == 0) ? g_b1h : g_b2h;

    constexpr int STA = MT * 72;             // A tile 96x64, pad 64->72
    constexpr int STB = 64 * 136;            // B tile 64x128, pad 128->136
    constexpr int STG = STA + STB;           // 15616 halfs / stage

    const int tid  = threadIdx.x;
    const int warp = tid >> 5;
    const int lane = tid & 31;
    const int bm0  = blockIdx.y * MT;
    const int bn0  = blockIdx.x * 128;

    #define LOAD_STAGE(s) do {                                                 \
        __half* st_ = smh + ((s) % 3) * STG;                                   \
        /* A: 96 rows x 8 chunks of 16B = 768 chunks, 6 per thread */          \
        _Pragma("unroll")                                                      \
        for (int j = 0; j < 6; ++j) {                                          \
            int ci = tid + 128 * j;                                            \
            int row = ci >> 3, ch = ci & 7;                                    \
            cpa16s(smem_u32(st_ + row * 72 + ch * 8),                          \
                   A + (size_t)(bm0 + row) * KH + (s) * 64 + ch * 8);          \
        }                                                                      \
        /* B: 64 rows x 16 chunks = 1024 chunks, 8 per thread */               \
        _Pragma("unroll")                                                      \
        for (int j = 0; j < 8; ++j) {                                          \
            int ci = tid + 128 * j;                                            \
            int row = ci >> 4, ch = ci & 15;                                   \
            cpa16s(smem_u32(st_ + STA + row * 136 + ch * 8),                   \
                   B + (size_t)((s) * 64 + row) * HID + bn0 + ch * 8);         \
        }                                                                      \
        asm volatile("cp.async.commit_group;" ::: "memory");                   \
    } while (0)

    const int mbase = (warp >> 1) * 48;     // warp tile 48x64
    const int nbase = (warp & 1) * 64;
    const int lrow  = lane & 15;
    const int lcol  = (lane >> 4) << 3;

    float acc[3][8][4];
    #pragma unroll
    for (int a = 0; a < 3; ++a)
        #pragma unroll
        for (int b = 0; b < 8; ++b)
            #pragma unroll
            for (int c = 0; c < 4; ++c) acc[a][b][c] = 0.f;

    LOAD_STAGE(0);
    LOAD_STAGE(1);

    constexpr int NIT = KH / 64;   // 16
    #pragma unroll 1
    for (int s = 0; s < NIT; ++s) {
        if (s + 1 < NIT) asm volatile("cp.async.wait_group 1;" ::: "memory");
        else             asm volatile("cp.async.wait_group 0;" ::: "memory");
        __syncthreads();

        const __half* st = smh + (s % 3) * STG;
        #pragma unroll
        for (int ks = 0; ks < 64; ks += 16) {
            unsigned bf[8][2];
            #pragma unroll
            for (int ntp = 0; ntp < 4; ++ntp) {
                unsigned t4[4];
                ldsm4t(t4, st + STA + (ks + lrow) * 136 + nbase + ntp * 16 + lcol);
                bf[ntp * 2][0]     = t4[0];  bf[ntp * 2][1]     = t4[1];
                bf[ntp * 2 + 1][0] = t4[2];  bf[ntp * 2 + 1][1] = t4[3];
            }
            unsigned af[3][4];
            #pragma unroll
            for (int mt = 0; mt < 3; ++mt)
                ldsm4(af[mt], st + (mbase + mt * 16 + lrow) * 72 + ks + lcol);
            #pragma unroll
            for (int mt = 0; mt < 3; ++mt)
                #pragma unroll
                for (int nt = 0; nt < 8; ++nt)
                    mma16816h(acc[mt][nt], af[mt], bf[nt]);
        }
        if (s + 2 < NIT) LOAD_STAGE(s + 2);
    }

    // ---- epilogue ----
    const int g  = lane >> 2;
    const int tg = lane & 3;
    #pragma unroll
    for (int mt = 0; mt < 3; ++mt) {
        #pragma unroll
        for (int nt = 0; nt < 8; ++nt) {
            int r0 = bm0 + mbase + mt * 16 + g;
            int r1 = r0 + 8;
            int c  = bn0 + nbase + nt * 8 + tg * 2;
            float* a4 = acc[mt][nt];
            if (MODE == 0) {
                __half2 v0 = __floats2half2_rn(a4[0], a4[1]);
                __half2 v1 = __floats2half2_rn(a4[2], a4[3]);
                if (r0 < NN) *(__half2*)&g_h1[(size_t)r0 * HID + c] = v0;
                if (r1 < NN) *(__half2*)&g_h1[(size_t)r1 * HID + c] = v1;
            } else {
                if (c < COUT) {
                    float2 v0 = make_float2(a4[0] + bias0[c], a4[1] + bias0[c + 1]);
                    float2 v1 = make_float2(a4[2] + bias0[c], a4[3] + bias0[c + 1]);
                    if (r0 < NN) {
                        *(float2*)&Cout[(size_t)r0 * COUT + c] = v0;                   // z
                        *(float2*)&Cout[(size_t)(NN + r0) * COUT + c] = v0;            // mu
                    }
                    if (r1 < NN) {
                        *(float2*)&Cout[(size_t)r1 * COUT + c] = v1;
                        *(float2*)&Cout[(size_t)(NN + r1) * COUT + c] = v1;
                    }
                } else {
                    int cs = c - COUT;
                    float2 v0 = make_float2(a4[0] + bias1[cs], a4[1] + bias1[cs + 1]);
                    float2 v1 = make_float2(a4[2] + bias1[cs], a4[3] + bias1[cs + 1]);
                    if (r0 < NN) *(float2*)&Cout[(size_t)(2 * NN + r0) * COUT + cs] = v0;  // logstd
                    if (r1 < NN) *(float2*)&Cout[(size_t)(2 * NN + r1) * COUT + cs] = v1;
                }
            }
        }
    }
    #undef LOAD_STAGE
}

// ---------------- aggregation (fp16 gather, f32 accumulate) ----------------
// agg1: g_h2 = fp16(leakyrelu(A_norm @ g_h1 + b1))
__global__ void __launch_bounds__(256)
k_agg1(const float* __restrict__ bias) {
    const int i = blockIdx.x;
    const int t = threadIdx.x;
    const float dv = g_dinv[i];
    const float sw = dv * dv;

    const __half2* self = (const __half2*)(g_h1 + (size_t)i * HID);
    float2 f0 = __half22float2(self[t]);
    float2 f1 = __half22float2(self[t + 256]);
    float a0 = sw * f0.x, a1 = sw * f0.y, a2 = sw * f1.x, a3 = sw * f1.y;

    const int beg = g_rowptr[i];
    const int end = g_rowptr[i + 1];
    #pragma unroll 2
    for (int e = beg; e < end; ++e) {
        const int   s = g_cols[e];
        const float w = g_wt[e];
        const __half2* r = (const __half2*)(g_h1 + (size_t)s * HID);
        float2 r0 = __half22float2(r[t]);
        float2 r1 = __half22float2(r[t + 256]);
        a0 = fmaf(w, r0.x, a0);
        a1 = fmaf(w, r0.y, a1);
        a2 = fmaf(w, r1.x, a2);
        a3 = fmaf(w, r1.y, a3);
    }
    a0 += bias[2 * t];       a0 = (a0 > 0.f) ? a0 : SLOPE * a0;
    a1 += bias[2 * t + 1];   a1 = (a1 > 0.f) ? a1 : SLOPE * a1;
    a2 += bias[2 * t + 512]; a2 = (a2 > 0.f) ? a2 : SLOPE * a2;
    a3 += bias[2 * t + 513]; a3 = (a3 > 0.f) ? a3 : SLOPE * a3;

    __half2* o = (__half2*)(g_h2 + (size_t)i * HID);
    o[t]       = __floats2half2_rn(a0, a1);
    o[t + 256] = __floats2half2_rn(a2, a3);
}

// agg2: g_a2h = fp16(A_norm @ g_h2)   (GEMM2 A input)
__global__ void __launch_bounds__(256)
k_agg2() {
    const int i = blockIdx.x;
    const int t = threadIdx.x;
    const float dv = g_dinv[i];
    const float sw = dv * dv;

    const __half2* self = (const __half2*)(g_h2 + (size_t)i * HID);
    float2 f0 = __half22float2(self[t]);
    float2 f1 = __half22float2(self[t + 256]);
    float a0 = sw * f0.x, a1 = sw * f0.y, a2 = sw * f1.x, a3 = sw * f1.y;

    const int beg = g_rowptr[i];
    const int end = g_rowptr[i + 1];
    #pragma unroll 2
    for (int e = beg; e < end; ++e) {
        const int   s = g_cols[e];
        const float w = g_wt[e];
        const __half2* r = (const __half2*)(g_h2 + (size_t)s * HID);
        float2 r0 = __half22float2(r[t]);
        float2 r1 = __half22float2(r[t + 256]);
        a0 = fmaf(w, r0.x, a0);
        a1 = fmaf(w, r0.y, a1);
        a2 = fmaf(w, r1.x, a2);
        a3 = fmaf(w, r1.y, a3);
    }

    __half2* o = (__half2*)(g_a2h + (size_t)i * KH);
    o[t]       = __floats2half2_rn(a0, a1);
    o[t + 256] = __floats2half2_rn(a2, a3);
}

// ---------------- launch ----------------
extern "C" void kernel_launch(void* const* d_in, const int* in_sizes, int n_in,
                              void* d_out, int out_size) {
    const float* x   = (const float*)d_in[0];
    const void*  edg = d_in[1];
    const float* W1  = (const float*)d_in[2];
    const float* b1  = (const float*)d_in[3];
    const float* Wm  = (const float*)d_in[4];
    const float* bm  = (const float*)d_in[5];
    const float* Ws  = (const float*)d_in[6];
    const float* bs  = (const float*)d_in[7];
    const float* gw  = (const float*)d_in[8];
    const float* gb  = (const float*)d_in[9];
    const float* gms = (const float*)d_in[10];
    float* out = (float*)d_out;

    constexpr int DSMEM = (MT * 72 + 64 * 136) * 3 * 2;   // 93696 bytes
    cudaFuncSetAttribute(k_mma<0>, cudaFuncAttributeMaxDynamicSharedMemorySize, DSMEM);
    cudaFuncSetAttribute(k_mma<1>, cudaFuncAttributeMaxDynamicSharedMemorySize, DSMEM);

    // graph preprocessing + norm stats (fused: detect->zero, dinv->scan)
    k_zero<<<(NN + 255) / 256, 256>>>((const int*)edg);
    k_convert<<<(EE + 255) / 256, 256>>>(edg);
    k_scan<<<1, 1024>>>();
    k_fill<<<(EE + 255) / 256, 256>>>();
    k_stats<<<200, 256>>>(x);
    k_fin<<<(CIN + 255) / 256, 256>>>(gw, gb, gms);

    // fp16 operand construction
    k_build_a1<<<(NN * CIN + 255) / 256, 256>>>(x);
    k_build_w<<<(CIN * HID + 255) / 256, 256>>>(W1, Wm, Ws);

    // layer 1: h = graphnorm(x) @ W1   (fp16 out)
    dim3 g1(HID / 128, MTILES);     // (8, 105)
    k_mma<0><<<g1, 128, DSMEM>>>(nullptr, nullptr, nullptr);

    // h2 = leakyrelu(A_norm @ h + b1);  A2 = A_norm @ h2
    k_agg1<<<NN, 256>>>(b1);
    k_agg2<<<NN, 256>>>();

    // layer 2: out = A2 @ [Wm|Ws] + bias   (z = mu duplicated)
    dim3 g2(HID / 128, MTILES);
    k_mma<1><<<g2, 128, DSMEM>>>(bm, bs, out);
}

// round 9
// speedup vs baseline: 4.4468x; 1.0900x over previous
#include <cuda_runtime.h>
#include <cuda_fp16.h>
#include <cstdint>

#define NN   10000
#define EE   160000
#define CIN  1024
#define HID  1024
#define COUT 512
#define KH   1024
#define MPAD 10112           // padded row allocation (>= 105*96 = 10080)
#define MT   96              // CTA M tile
#define MTILES 105           // ceil(10000/96)
#define GN_EPS 1e-5f
#define SLOPE  0.1f

// ---------------- scratch (static device globals; no runtime alloc) ----------------
__device__ __half g_h1[(size_t)NN * HID];           // h = GEMM1 out (fp16)
__device__ __half g_h2[(size_t)NN * HID];           // agg1 out (fp16)
__device__ __half g_a1h[(size_t)MPAD * KH];         // GEMM1 A (fp16)
__device__ __half g_a2h[(size_t)MPAD * KH];         // GEMM2 A = agg2 out (fp16)
__device__ __half g_b1h[(size_t)KH * HID];          // GEMM1 B [k][n] = fp16(W1)
__device__ __half g_b2h[(size_t)KH * HID];          // GEMM2 B [k][n] = fp16([Wm|Ws])
__device__ float g_alpha[CIN];
__device__ float g_beta[CIN];
__device__ float g_sum[CIN];
__device__ float g_sumsq[CIN];
__device__ float g_dinv[NN];
__device__ int   g_cnt[NN];
__device__ int   g_rowptr[NN + 1];
__device__ int   g_cur[NN];
__device__ int   g_srcs[EE];
__device__ int   g_dsts[EE];
__device__ int   g_cols[EE];
__device__ float g_wt[EE];
__device__ int   g_is64;

// ---------------- PTX helpers ----------------
__device__ __forceinline__ unsigned smem_u32(const void* p) {
    return (unsigned)__cvta_generic_to_shared(p);
}
__device__ __forceinline__ void cpa16s(unsigned dst, const void* src) {
    asm volatile("cp.async.cg.shared.global [%0], [%1], 16;" :: "r"(dst), "l"(src) : "memory");
}
__device__ __forceinline__ void ldsm4(unsigned* r, const void* p) {
    unsigned a = smem_u32(p);
    asm volatile("ldmatrix.sync.aligned.m8n8.x4.shared.b16 {%0,%1,%2,%3}, [%4];"
                 : "=r"(r[0]), "=r"(r[1]), "=r"(r[2]), "=r"(r[3]) : "r"(a));
}
__device__ __forceinline__ void ldsm4t(unsigned* r, const void* p) {
    unsigned a = smem_u32(p);
    asm volatile("ldmatrix.sync.aligned.m8n8.x4.trans.shared.b16 {%0,%1,%2,%3}, [%4];"
                 : "=r"(r[0]), "=r"(r[1]), "=r"(r[2]), "=r"(r[3]) : "r"(a));
}
__device__ __forceinline__ void mma16816h(float* d, const unsigned* a, const unsigned* b) {
    asm volatile("mma.sync.aligned.m16n8k16.row.col.f32.f16.f16.f32 "
                 "{%0,%1,%2,%3}, {%4,%5,%6,%7}, {%8,%9}, {%0,%1,%2,%3};"
                 : "+f"(d[0]), "+f"(d[1]), "+f"(d[2]), "+f"(d[3])
                 : "r"(a[0]), "r"(a[1]), "r"(a[2]), "r"(a[3]), "r"(b[0]), "r"(b[1]));
}

// ---------------- small utility kernels ----------------
// zero counters + edge dtype detection fused
__global__ void k_zero(const int* __restrict__ e) {
    int i = blockIdx.x * blockDim.x + threadIdx.x;
    if (i < CIN) { g_sum[i] = 0.f; g_sumsq[i] = 0.f; }
    if (i < NN)  { g_cnt[i] = 0; }
    if (i == 0) {
        int is64 = 1;
        for (int j = 0; j < 64; ++j)
            if (e[2 * j + 1] != 0) { is64 = 0; break; }
        g_is64 = is64;
    }
}

// convert + degree count fused
__global__ void k_convert(const void* __restrict__ edges) {
    int i = blockIdx.x * blockDim.x + threadIdx.x;
    if (i >= EE) return;
    int s, d;
    if (g_is64) {
        const long long* e = (const long long*)edges;
        s = (int)e[i];  d = (int)e[EE + i];
    } else {
        const int* e = (const int*)edges;
        s = e[i];  d = e[EE + i];
    }
    g_srcs[i] = s;  g_dsts[i] = d;
    atomicAdd(&g_cnt[d], 1);
}

// blocked single-pass exclusive scan (1024 thr x 10 elems) -> rowptr/cur/dinv
__global__ void k_scan() {
    __shared__ int sh[1024];
    const int t = threadIdx.x;
    const int base = t * 10;
    int v[10], loc[10], run = 0;
    #pragma unroll
    for (int j = 0; j < 10; ++j) {
        int idx = base + j;
        v[j] = (idx < NN) ? g_cnt[idx] : 0;
        loc[j] = run;
        run += v[j];
    }
    sh[t] = run;
    __syncthreads();
    for (int off = 1; off < 1024; off <<= 1) {
        int add = (t >= off) ? sh[t - off] : 0;
        __syncthreads();
        sh[t] += add;
        __syncthreads();
    }
    int pre = (t > 0) ? sh[t - 1] : 0;
    #pragma unroll
    for (int j = 0; j < 10; ++j) {
        int idx = base + j;
        if (idx < NN) {
            int ex = pre + loc[j];
            g_rowptr[idx] = ex;
            g_cur[idx]    = ex;
            g_dinv[idx]   = rsqrtf((float)(v[j] + 1));   // +1 self loop
        }
    }
    if (t == 1023) g_rowptr[NN] = sh[1023];
}

__global__ void k_fill() {
    int i = blockIdx.x * blockDim.x + threadIdx.x;
    if (i >= EE) return;
    int d = g_dsts[i];
    int s = g_srcs[i];
    int pos = atomicAdd(&g_cur[d], 1);
    g_cols[pos] = s;
    g_wt[pos]   = g_dinv[s] * g_dinv[d];
}

__global__ void k_stats(const float* __restrict__ x) {
    const int t = threadIdx.x;
    float s0 = 0.f, s1 = 0.f, s2 = 0.f, s3 = 0.f;
    float q0 = 0.f, q1 = 0.f, q2 = 0.f, q3 = 0.f;
    for (int r = blockIdx.x; r < NN; r += gridDim.x) {
        const float* row = x + (size_t)r * CIN;
        float v0 = row[t];       s0 += v0; q0 += v0 * v0;
        float v1 = row[t + 256]; s1 += v1; q1 += v1 * v1;
        float v2 = row[t + 512]; s2 += v2; q2 += v2 * v2;
        float v3 = row[t + 768]; s3 += v3; q3 += v3 * v3;
    }
    atomicAdd(&g_sum[t],       s0); atomicAdd(&g_sumsq[t],       q0);
    atomicAdd(&g_sum[t + 256], s1); atomicAdd(&g_sumsq[t + 256], q1);
    atomicAdd(&g_sum[t + 512], s2); atomicAdd(&g_sumsq[t + 512], q2);
    atomicAdd(&g_sum[t + 768], s3); atomicAdd(&g_sumsq[t + 768], q3);
}

__global__ void k_fin(const float* __restrict__ gw,
                      const float* __restrict__ gb,
                      const float* __restrict__ gms) {
    int i = blockIdx.x * blockDim.x + threadIdx.x;
    if (i >= CIN) return;
    float mean = g_sum[i]   * (1.0f / NN);
    float ex2  = g_sumsq[i] * (1.0f / NN);
    float s    = gms[i];
    float var  = ex2 - 2.f * s * mean * mean + s * s * mean * mean;
    float rstd = rsqrtf(var + GN_EPS);
    float al   = rstd * gw[i];
    g_alpha[i] = al;
    g_beta[i]  = gb[i] - s * mean * al;
}

// A1 = fp16(affine(x)), 4-wide vectorized
__global__ void k_build_a1(const float* __restrict__ x) {
    int i = blockIdx.x * blockDim.x + threadIdx.x;    // over NN*CIN/4
    if (i >= NN * CIN / 4) return;
    int k4 = (i & 255) << 2;
    float4 xv = ((const float4*)x)[i];
    float a0 = g_alpha[k4],     a1 = g_alpha[k4 + 1];
    float a2 = g_alpha[k4 + 2], a3 = g_alpha[k4 + 3];
    float b0 = g_beta[k4],      b1 = g_beta[k4 + 1];
    float b2 = g_beta[k4 + 2],  b3 = g_beta[k4 + 3];
    __half2 h0 = __floats2half2_rn(fmaf(xv.x, a0, b0), fmaf(xv.y, a1, b1));
    __half2 h1 = __floats2half2_rn(fmaf(xv.z, a2, b2), fmaf(xv.w, a3, b3));
    __half2* o = (__half2*)g_a1h + (size_t)i * 2;
    o[0] = h0;  o[1] = h1;
}

// B planes, 4-wide vectorized: g_b1h = fp16(W1); g_b2h = fp16([Wm|Ws])
__global__ void k_build_w(const float* __restrict__ W1,
                          const float* __restrict__ Wm,
                          const float* __restrict__ Ws) {
    int i = blockIdx.x * blockDim.x + threadIdx.x;    // over CIN*HID/4
    if (i >= CIN * HID / 4) return;
    int k  = i >> 8;
    int n4 = (i & 255) << 2;
    float4 w1 = ((const float4*)W1)[i];
    __half2* o1 = (__half2*)g_b1h + (size_t)i * 2;
    o1[0] = __floats2half2_rn(w1.x, w1.y);
    o1[1] = __floats2half2_rn(w1.z, w1.w);
    float4 w2 = (n4 < COUT)
        ? *(const float4*)(Wm + (size_t)k * COUT + n4)
        : *(const float4*)(Ws + (size_t)k * COUT + n4 - COUT);
    __half2* o2 = (__half2*)g_b2h + (size_t)i * 2;
    o2[0] = __floats2half2_rn(w2.x, w2.y);
    o2[1] = __floats2half2_rn(w2.z, w2.w);
}

// ---------------- fp16 tensor-core GEMM ----------------
// CTA 96x128 (wave-balanced: 840 CTAs / 296 concurrent = 2.84 waves),
// 4 warps of 48x64, BK=64, 3-stage cp.async ring, K=1024.
// MODE 0: g_h1 (fp16) = A1 @ B1        MODE 1: out (f32) = A2 @ B2 + bias
template <int MODE>
__global__ void __launch_bounds__(128, 2)
k_mma(const float* __restrict__ bias0, const float* __restrict__ bias1,
      float* __restrict__ Cout)
{
    extern __shared__ __half smh[];
    const __half* __restrict__ A = (MODE == 0) ? g_a1h : g_a2h;
    const __half* __restrict__ B = (MODE == 0) ? g_b1h : g_b2h;

    constexpr int STA = MT * 72;             // A tile 96x64, pad 64->72
    constexpr int STB = 64 * 136;            // B tile 64x128, pad 128->136
    constexpr int STG = STA + STB;           // 15616 halfs / stage

    const int tid  = threadIdx.x;
    const int warp = tid >> 5;
    const int lane = tid & 31;
    const int bm0  = blockIdx.y * MT;
    const int bn0  = blockIdx.x * 128;

    #define LOAD_STAGE(s) do {                                                 \
        __half* st_ = smh + ((s) % 3) * STG;                                   \
        _Pragma("unroll")                                                      \
        for (int j = 0; j < 6; ++j) {                                          \
            int ci = tid + 128 * j;                                            \
            int row = ci >> 3, ch = ci & 7;                                    \
            cpa16s(smem_u32(st_ + row * 72 + ch * 8),                          \
                   A + (size_t)(bm0 + row) * KH + (s) * 64 + ch * 8);          \
        }                                                                      \
        _Pragma("unroll")                                                      \
        for (int j = 0; j < 8; ++j) {                                          \
            int ci = tid + 128 * j;                                            \
            int row = ci >> 4, ch = ci & 15;                                   \
            cpa16s(smem_u32(st_ + STA + row * 136 + ch * 8),                   \
                   B + (size_t)((s) * 64 + row) * HID + bn0 + ch * 8);         \
        }                                                                      \
        asm volatile("cp.async.commit_group;" ::: "memory");                   \
    } while (0)

    const int mbase = (warp >> 1) * 48;     // warp tile 48x64
    const int nbase = (warp & 1) * 64;
    const int lrow  = lane & 15;
    const int lcol  = (lane >> 4) << 3;

    float acc[3][8][4];
    #pragma unroll
    for (int a = 0; a < 3; ++a)
        #pragma unroll
        for (int b = 0; b < 8; ++b)
            #pragma unroll
            for (int c = 0; c < 4; ++c) acc[a][b][c] = 0.f;

    LOAD_STAGE(0);
    LOAD_STAGE(1);

    constexpr int NIT = KH / 64;   // 16
    #pragma unroll 1
    for (int s = 0; s < NIT; ++s) {
        if (s + 1 < NIT) asm volatile("cp.async.wait_group 1;" ::: "memory");
        else             asm volatile("cp.async.wait_group 0;" ::: "memory");
        __syncthreads();

        const __half* st = smh + (s % 3) * STG;
        #pragma unroll
        for (int ks = 0; ks < 64; ks += 16) {
            unsigned bf[8][2];
            #pragma unroll
            for (int ntp = 0; ntp < 4; ++ntp) {
                unsigned t4[4];
                ldsm4t(t4, st + STA + (ks + lrow) * 136 + nbase + ntp * 16 + lcol);
                bf[ntp * 2][0]     = t4[0];  bf[ntp * 2][1]     = t4[1];
                bf[ntp * 2 + 1][0] = t4[2];  bf[ntp * 2 + 1][1] = t4[3];
            }
            unsigned af[3][4];
            #pragma unroll
            for (int mt = 0; mt < 3; ++mt)
                ldsm4(af[mt], st + (mbase + mt * 16 + lrow) * 72 + ks + lcol);
            #pragma unroll
            for (int mt = 0; mt < 3; ++mt)
                #pragma unroll
                for (int nt = 0; nt < 8; ++nt)
                    mma16816h(acc[mt][nt], af[mt], bf[nt]);
        }
        if (s + 2 < NIT) LOAD_STAGE(s + 2);
    }

    // ---- epilogue ----
    const int g  = lane >> 2;
    const int tg = lane & 3;
    #pragma unroll
    for (int mt = 0; mt < 3; ++mt) {
        #pragma unroll
        for (int nt = 0; nt < 8; ++nt) {
            int r0 = bm0 + mbase + mt * 16 + g;
            int r1 = r0 + 8;
            int c  = bn0 + nbase + nt * 8 + tg * 2;
            float* a4 = acc[mt][nt];
            if (MODE == 0) {
                __half2 v0 = __floats2half2_rn(a4[0], a4[1]);
                __half2 v1 = __floats2half2_rn(a4[2], a4[3]);
                if (r0 < NN) *(__half2*)&g_h1[(size_t)r0 * HID + c] = v0;
                if (r1 < NN) *(__half2*)&g_h1[(size_t)r1 * HID + c] = v1;
            } else {
                if (c < COUT) {
                    float2 v0 = make_float2(a4[0] + bias0[c], a4[1] + bias0[c + 1]);
                    float2 v1 = make_float2(a4[2] + bias0[c], a4[3] + bias0[c + 1]);
                    if (r0 < NN) {
                        *(float2*)&Cout[(size_t)r0 * COUT + c] = v0;                   // z
                        *(float2*)&Cout[(size_t)(NN + r0) * COUT + c] = v0;            // mu
                    }
                    if (r1 < NN) {
                        *(float2*)&Cout[(size_t)r1 * COUT + c] = v1;
                        *(float2*)&Cout[(size_t)(NN + r1) * COUT + c] = v1;
                    }
                } else {
                    int cs = c - COUT;
                    float2 v0 = make_float2(a4[0] + bias1[cs], a4[1] + bias1[cs + 1]);
                    float2 v1 = make_float2(a4[2] + bias1[cs], a4[3] + bias1[cs + 1]);
                    if (r0 < NN) *(float2*)&Cout[(size_t)(2 * NN + r0) * COUT + cs] = v0;  // logstd
                    if (r1 < NN) *(float2*)&Cout[(size_t)(2 * NN + r1) * COUT + cs] = v1;
                }
            }
        }
    }
    #undef LOAD_STAGE
}

// ---------------- aggregation (fp16 gather, f32 accumulate) ----------------
__global__ void __launch_bounds__(256)
k_agg1(const float* __restrict__ bias) {
    const int i = blockIdx.x;
    const int t = threadIdx.x;
    const float dv = g_dinv[i];
    const float sw = dv * dv;

    const __half2* self = (const __half2*)(g_h1 + (size_t)i * HID);
    float2 f0 = __half22float2(self[t]);
    float2 f1 = __half22float2(self[t + 256]);
    float a0 = sw * f0.x, a1 = sw * f0.y, a2 = sw * f1.x, a3 = sw * f1.y;

    const int beg = g_rowptr[i];
    const int end = g_rowptr[i + 1];
    #pragma unroll 2
    for (int e = beg; e < end; ++e) {
        const int   s = g_cols[e];
        const float w = g_wt[e];
        const __half2* r = (const __half2*)(g_h1 + (size_t)s * HID);
        float2 r0 = __half22float2(r[t]);
        float2 r1 = __half22float2(r[t + 256]);
        a0 = fmaf(w, r0.x, a0);
        a1 = fmaf(w, r0.y, a1);
        a2 = fmaf(w, r1.x, a2);
        a3 = fmaf(w, r1.y, a3);
    }
    a0 += bias[2 * t];       a0 = (a0 > 0.f) ? a0 : SLOPE * a0;
    a1 += bias[2 * t + 1];   a1 = (a1 > 0.f) ? a1 : SLOPE * a1;
    a2 += bias[2 * t + 512]; a2 = (a2 > 0.f) ? a2 : SLOPE * a2;
    a3 += bias[2 * t + 513]; a3 = (a3 > 0.f) ? a3 : SLOPE * a3;

    __half2* o = (__half2*)(g_h2 + (size_t)i * HID);
    o[t]       = __floats2half2_rn(a0, a1);
    o[t + 256] = __floats2half2_rn(a2, a3);
}

__global__ void __launch_bounds__(256)
k_agg2() {
    const int i = blockIdx.x;
    const int t = threadIdx.x;
    const float dv = g_dinv[i];
    const float sw = dv * dv;

    const __half2* self = (const __half2*)(g_h2 + (size_t)i * HID);
    float2 f0 = __half22float2(self[t]);
    float2 f1 = __half22float2(self[t + 256]);
    float a0 = sw * f0.x, a1 = sw * f0.y, a2 = sw * f1.x, a3 = sw * f1.y;

    const int beg = g_rowptr[i];
    const int end = g_rowptr[i + 1];
    #pragma unroll 2
    for (int e = beg; e < end; ++e) {
        const int   s = g_cols[e];
        const float w = g_wt[e];
        const __half2* r = (const __half2*)(g_h2 + (size_t)s * HID);
        float2 r0 = __half22float2(r[t]);
        float2 r1 = __half22float2(r[t + 256]);
        a0 = fmaf(w, r0.x, a0);
        a1 = fmaf(w, r0.y, a1);
        a2 = fmaf(w, r1.x, a2);
        a3 = fmaf(w, r1.y, a3);
    }

    __half2* o = (__half2*)(g_a2h + (size_t)i * KH);
    o[t]       = __floats2half2_rn(a0, a1);
    o[t + 256] = __floats2half2_rn(a2, a3);
}

// ---------------- launch ----------------
extern "C" void kernel_launch(void* const* d_in, const int* in_sizes, int n_in,
                              void* d_out, int out_size) {
    const float* x   = (const float*)d_in[0];
    const void*  edg = d_in[1];
    const float* W1  = (const float*)d_in[2];
    const float* b1  = (const float*)d_in[3];
    const float* Wm  = (const float*)d_in[4];
    const float* bm  = (const float*)d_in[5];
    const float* Ws  = (const float*)d_in[6];
    const float* bs  = (const float*)d_in[7];
    const float* gw  = (const float*)d_in[8];
    const float* gb  = (const float*)d_in[9];
    const float* gms = (const float*)d_in[10];
    float* out = (float*)d_out;

    // Lazily create side stream + fork/join events on the first call (the
    // correctness run, outside graph capture). No device memory is allocated;
    // every call issues the identical launch DAG.
    static cudaStream_t s_edge = nullptr;
    static cudaEvent_t  ev_fork = nullptr, ev_join = nullptr;
    if (s_edge == nullptr) {
        cudaStreamCreateWithFlags(&s_edge, cudaStreamNonBlocking);
        cudaEventCreateWithFlags(&ev_fork, cudaEventDisableTiming);
        cudaEventCreateWithFlags(&ev_join, cudaEventDisableTiming);
    }

    constexpr int DSMEM = (MT * 72 + 64 * 136) * 3 * 2;   // 93696 bytes
    cudaFuncSetAttribute(k_mma<0>, cudaFuncAttributeMaxDynamicSharedMemorySize, DSMEM);
    cudaFuncSetAttribute(k_mma<1>, cudaFuncAttributeMaxDynamicSharedMemorySize, DSMEM);

    // common root: zero counters/sums + dtype detect
    k_zero<<<(NN + 255) / 256, 256>>>((const int*)edg);
    cudaEventRecord(ev_fork, 0);

    // ---- side stream: edge chain (feeds only the aggregations) ----
    cudaStreamWaitEvent(s_edge, ev_fork, 0);
    k_convert<<<(EE + 255) / 256, 256, 0, s_edge>>>(edg);
    k_scan<<<1, 1024, 0, s_edge>>>();
    k_fill<<<(EE + 255) / 256, 256, 0, s_edge>>>();
    cudaEventRecord(ev_join, s_edge);

    // ---- main stream: dense chain ----
    k_stats<<<200, 256>>>(x);
    k_fin<<<(CIN + 255) / 256, 256>>>(gw, gb, gms);
    k_build_a1<<<(NN * CIN / 4 + 255) / 256, 256>>>(x);
    k_build_w<<<(CIN * HID / 4 + 255) / 256, 256>>>(W1, Wm, Ws);

    // layer 1: h = graphnorm(x) @ W1   (fp16 out)
    dim3 g1(HID / 128, MTILES);     // (8, 105)
    k_mma<0><<<g1, 128, DSMEM>>>(nullptr, nullptr, nullptr);

    // join: aggregations need the edge CSR
    cudaStreamWaitEvent(0, ev_join, 0);
    k_agg1<<<NN, 256>>>(b1);
    k_agg2<<<NN, 256>>>();

    // layer 2: out = A2 @ [Wm|Ws] + bias   (z = mu duplicated)
    dim3 g2(HID / 128, MTILES);
    k_mma<1><<<g2, 128, DSMEM>>>(bm, bs, out);
}

// round 10
// speedup vs baseline: 4.6346x; 1.0422x over previous
#include <cuda_runtime.h>
#include <cuda_fp16.h>
#include <cstdint>

#define NN   10000
#define EE   160000
#define CIN  1024
#define HID  1024
#define COUT 512
#define KH   1024
#define MPAD 10112           // padded row allocation (>= 105*96 = 10080)
#define MT   96              // CTA M tile
#define NT2  256             // CTA N tile
#define MTILES 105           // ceil(10000/96)
#define GN_EPS 1e-5f
#define SLOPE  0.1f

// ---------------- scratch (static device globals; no runtime alloc) ----------------
__device__ __half g_h1[(size_t)NN * HID];           // h = GEMM1 out (fp16)
__device__ __half g_h2[(size_t)NN * HID];           // agg1 out (fp16)
__device__ __half g_a1h[(size_t)MPAD * KH];         // GEMM1 A (fp16)
__device__ __half g_a2h[(size_t)MPAD * KH];         // GEMM2 A = agg2 out (fp16)
__device__ __half g_b1h[(size_t)KH * HID];          // GEMM1 B [k][n] = fp16(W1)
__device__ __half g_b2h[(size_t)KH * HID];          // GEMM2 B [k][n] = fp16([Wm|Ws])
__device__ float g_alpha[CIN];
__device__ float g_beta[CIN];
__device__ float g_sum[CIN];
__device__ float g_sumsq[CIN];
__device__ float g_dinv[NN];
__device__ int   g_cnt[NN];
__device__ int   g_rowptr[NN + 1];
__device__ int   g_cur[NN];
__device__ int   g_srcs[EE];
__device__ int   g_dsts[EE];
__device__ int   g_cols[EE];
__device__ float g_wt[EE];
__device__ int   g_is64;

// ---------------- PTX helpers ----------------
__device__ __forceinline__ unsigned smem_u32(const void* p) {
    return (unsigned)__cvta_generic_to_shared(p);
}
__device__ __forceinline__ void cpa16s(unsigned dst, const void* src) {
    asm volatile("cp.async.cg.shared.global [%0], [%1], 16;" :: "r"(dst), "l"(src) : "memory");
}
__device__ __forceinline__ void ldsm4(unsigned* r, const void* p) {
    unsigned a = smem_u32(p);
    asm volatile("ldmatrix.sync.aligned.m8n8.x4.shared.b16 {%0,%1,%2,%3}, [%4];"
                 : "=r"(r[0]), "=r"(r[1]), "=r"(r[2]), "=r"(r[3]) : "r"(a));
}
__device__ __forceinline__ void ldsm4t(unsigned* r, const void* p) {
    unsigned a = smem_u32(p);
    asm volatile("ldmatrix.sync.aligned.m8n8.x4.trans.shared.b16 {%0,%1,%2,%3}, [%4];"
                 : "=r"(r[0]), "=r"(r[1]), "=r"(r[2]), "=r"(r[3]) : "r"(a));
}
__device__ __forceinline__ void mma16816h(float* d, const unsigned* a, const unsigned* b) {
    asm volatile("mma.sync.aligned.m16n8k16.row.col.f32.f16.f16.f32 "
                 "{%0,%1,%2,%3}, {%4,%5,%6,%7}, {%8,%9}, {%0,%1,%2,%3};"
                 : "+f"(d[0]), "+f"(d[1]), "+f"(d[2]), "+f"(d[3])
                 : "r"(a[0]), "r"(a[1]), "r"(a[2]), "r"(a[3]), "r"(b[0]), "r"(b[1]));
}

// ---------------- small utility kernels ----------------
// zero counters + edge dtype detection fused
__global__ void k_zero(const int* __restrict__ e) {
    int i = blockIdx.x * blockDim.x + threadIdx.x;
    if (i < CIN) { g_sum[i] = 0.f; g_sumsq[i] = 0.f; }
    if (i < NN)  { g_cnt[i] = 0; }
    if (i == 0) {
        int is64 = 1;
        for (int j = 0; j < 64; ++j)
            if (e[2 * j + 1] != 0) { is64 = 0; break; }
        g_is64 = is64;
    }
}

// convert + degree count fused
__global__ void k_convert(const void* __restrict__ edges) {
    int i = blockIdx.x * blockDim.x + threadIdx.x;
    if (i >= EE) return;
    int s, d;
    if (g_is64) {
        const long long* e = (const long long*)edges;
        s = (int)e[i];  d = (int)e[EE + i];
    } else {
        const int* e = (const int*)edges;
        s = e[i];  d = e[EE + i];
    }
    g_srcs[i] = s;  g_dsts[i] = d;
    atomicAdd(&g_cnt[d], 1);
}

// blocked single-pass exclusive scan (1024 thr x 10 elems) -> rowptr/cur/dinv
__global__ void k_scan() {
    __shared__ int sh[1024];
    const int t = threadIdx.x;
    const int base = t * 10;
    int v[10], loc[10], run = 0;
    #pragma unroll
    for (int j = 0; j < 10; ++j) {
        int idx = base + j;
        v[j] = (idx < NN) ? g_cnt[idx] : 0;
        loc[j] = run;
        run += v[j];
    }
    sh[t] = run;
    __syncthreads();
    for (int off = 1; off < 1024; off <<= 1) {
        int add = (t >= off) ? sh[t - off] : 0;
        __syncthreads();
        sh[t] += add;
        __syncthreads();
    }
    int pre = (t > 0) ? sh[t - 1] : 0;
    #pragma unroll
    for (int j = 0; j < 10; ++j) {
        int idx = base + j;
        if (idx < NN) {
            int ex = pre + loc[j];
            g_rowptr[idx] = ex;
            g_cur[idx]    = ex;
            g_dinv[idx]   = rsqrtf((float)(v[j] + 1));   // +1 self loop
        }
    }
    if (t == 1023) g_rowptr[NN] = sh[1023];
}

__global__ void k_fill() {
    int i = blockIdx.x * blockDim.x + threadIdx.x;
    if (i >= EE) return;
    int d = g_dsts[i];
    int s = g_srcs[i];
    int pos = atomicAdd(&g_cur[d], 1);
    g_cols[pos] = s;
    g_wt[pos]   = g_dinv[s] * g_dinv[d];
}

__global__ void k_stats(const float* __restrict__ x) {
    const int t = threadIdx.x;
    float s0 = 0.f, s1 = 0.f, s2 = 0.f, s3 = 0.f;
    float q0 = 0.f, q1 = 0.f, q2 = 0.f, q3 = 0.f;
    for (int r = blockIdx.x; r < NN; r += gridDim.x) {
        const float* row = x + (size_t)r * CIN;
        float v0 = row[t];       s0 += v0; q0 += v0 * v0;
        float v1 = row[t + 256]; s1 += v1; q1 += v1 * v1;
        float v2 = row[t + 512]; s2 += v2; q2 += v2 * v2;
        float v3 = row[t + 768]; s3 += v3; q3 += v3 * v3;
    }
    atomicAdd(&g_sum[t],       s0); atomicAdd(&g_sumsq[t],       q0);
    atomicAdd(&g_sum[t + 256], s1); atomicAdd(&g_sumsq[t + 256], q1);
    atomicAdd(&g_sum[t + 512], s2); atomicAdd(&g_sumsq[t + 512], q2);
    atomicAdd(&g_sum[t + 768], s3); atomicAdd(&g_sumsq[t + 768], q3);
}

__global__ void k_fin(const float* __restrict__ gw,
                      const float* __restrict__ gb,
                      const float* __restrict__ gms) {
    int i = blockIdx.x * blockDim.x + threadIdx.x;
    if (i >= CIN) return;
    float mean = g_sum[i]   * (1.0f / NN);
    float ex2  = g_sumsq[i] * (1.0f / NN);
    float s    = gms[i];
    float var  = ex2 - 2.f * s * mean * mean + s * s * mean * mean;
    float rstd = rsqrtf(var + GN_EPS);
    float al   = rstd * gw[i];
    g_alpha[i] = al;
    g_beta[i]  = gb[i] - s * mean * al;
}

// A1 = fp16(affine(x)), 4-wide vectorized
__global__ void k_build_a1(const float* __restrict__ x) {
    int i = blockIdx.x * blockDim.x + threadIdx.x;    // over NN*CIN/4
    if (i >= NN * CIN / 4) return;
    int k4 = (i & 255) << 2;
    float4 xv = ((const float4*)x)[i];
    float a0 = g_alpha[k4],     a1 = g_alpha[k4 + 1];
    float a2 = g_alpha[k4 + 2], a3 = g_alpha[k4 + 3];
    float b0 = g_beta[k4],      b1 = g_beta[k4 + 1];
    float b2 = g_beta[k4 + 2],  b3 = g_beta[k4 + 3];
    __half2 h0 = __floats2half2_rn(fmaf(xv.x, a0, b0), fmaf(xv.y, a1, b1));
    __half2 h1 = __floats2half2_rn(fmaf(xv.z, a2, b2), fmaf(xv.w, a3, b3));
    __half2* o = (__half2*)g_a1h + (size_t)i * 2;
    o[0] = h0;  o[1] = h1;
}

// B planes, 4-wide vectorized: g_b1h = fp16(W1); g_b2h = fp16([Wm|Ws])
__global__ void k_build_w(const float* __restrict__ W1,
                          const float* __restrict__ Wm,
                          const float* __restrict__ Ws) {
    int i = blockIdx.x * blockDim.x + threadIdx.x;    // over CIN*HID/4
    if (i >= CIN * HID / 4) return;
    int k  = i >> 8;
    int n4 = (i & 255) << 2;
    float4 w1 = ((const float4*)W1)[i];
    __half2* o1 = (__half2*)g_b1h + (size_t)i * 2;
    o1[0] = __floats2half2_rn(w1.x, w1.y);
    o1[1] = __floats2half2_rn(w1.z, w1.w);
    float4 w2 = (n4 < COUT)
        ? *(const float4*)(Wm + (size_t)k * COUT + n4)
        : *(const float4*)(Ws + (size_t)k * COUT + n4 - COUT);
    __half2* o2 = (__half2*)g_b2h + (size_t)i * 2;
    o2[0] = __floats2half2_rn(w2.x, w2.y);
    o2[1] = __floats2half2_rn(w2.z, w2.w);
}

// ---------------- fp16 tensor-core GEMM ----------------
// CTA 96x256, 256 threads (8 warps of 48x64), BK=64, 3-stage cp.async ring.
// Grid 4x105 = 420 CTAs, 1 CTA/SM (143KB smem) -> MMA-bound (B smem traffic/MAC halved).
// MODE 0: g_h1 (fp16) = A1 @ B1        MODE 1: out (f32) = A2 @ B2 + bias
template <int MODE>
__global__ void __launch_bounds__(256, 1)
k_mma(const float* __restrict__ bias0, const float* __restrict__ bias1,
      float* __restrict__ Cout)
{
    extern __shared__ __half smh[];
    const __half* __restrict__ A = (MODE == 0) ? g_a1h : g_a2h;
    const __half* __restrict__ B = (MODE == 0) ? g_b1h : g_b2h;

    constexpr int STA = MT * 72;             // A tile 96x64, pad 64->72   (stride 144B ≡ 16 mod 128)
    constexpr int STB = 64 * 264;            // B tile 64x256, pad 256->264 (stride 528B ≡ 16 mod 128)
    constexpr int STG = STA + STB;           // 23808 halfs / stage

    const int tid  = threadIdx.x;
    const int warp = tid >> 5;
    const int lane = tid & 31;
    const int bm0  = blockIdx.y * MT;
    const int bn0  = blockIdx.x * NT2;

    #define LOAD_STAGE(s) do {                                                 \
        __half* st_ = smh + ((s) % 3) * STG;                                   \
        /* A: 96 rows x 8 chunks of 16B = 768 chunks, 3 per thread */          \
        _Pragma("unroll")                                                      \
        for (int j = 0; j < 3; ++j) {                                          \
            int ci = tid + 256 * j;                                            \
            int row = ci >> 3, ch = ci & 7;                                    \
            cpa16s(smem_u32(st_ + row * 72 + ch * 8),                          \
                   A + (size_t)(bm0 + row) * KH + (s) * 64 + ch * 8);          \
        }                                                                      \
        /* B: 64 rows x 32 chunks = 2048 chunks, 8 per thread */               \
        _Pragma("unroll")                                                      \
        for (int j = 0; j < 8; ++j) {                                          \
            int ci = tid + 256 * j;                                            \
            int row = ci >> 5, ch = ci & 31;                                   \
            cpa16s(smem_u32(st_ + STA + row * 264 + ch * 8),                   \
                   B + (size_t)((s) * 64 + row) * HID + bn0 + ch * 8);         \
        }                                                                      \
        asm volatile("cp.async.commit_group;" ::: "memory");                   \
    } while (0)

    const int mbase = (warp >> 2) * 48;     // warp tile 48x64, warp grid 2m x 4n
    const int nbase = (warp & 3) * 64;
    const int lrow  = lane & 15;
    const int lcol  = (lane >> 4) << 3;

    float acc[3][8][4];
    #pragma unroll
    for (int a = 0; a < 3; ++a)
        #pragma unroll
        for (int b = 0; b < 8; ++b)
            #pragma unroll
            for (int c = 0; c < 4; ++c) acc[a][b][c] = 0.f;

    LOAD_STAGE(0);
    LOAD_STAGE(1);

    constexpr int NIT = KH / 64;   // 16
    #pragma unroll 1
    for (int s = 0; s < NIT; ++s) {
        if (s + 1 < NIT) asm volatile("cp.async.wait_group 1;" ::: "memory");
        else             asm volatile("cp.async.wait_group 0;" ::: "memory");
        __syncthreads();

        const __half* st = smh + (s % 3) * STG;
        #pragma unroll
        for (int ks = 0; ks < 64; ks += 16) {
            unsigned bf[8][2];
            #pragma unroll
            for (int ntp = 0; ntp < 4; ++ntp) {
                unsigned t4[4];
                ldsm4t(t4, st + STA + (ks + lrow) * 264 + nbase + ntp * 16 + lcol);
                bf[ntp * 2][0]     = t4[0];  bf[ntp * 2][1]     = t4[1];
                bf[ntp * 2 + 1][0] = t4[2];  bf[ntp * 2 + 1][1] = t4[3];
            }
            unsigned af[3][4];
            #pragma unroll
            for (int mt = 0; mt < 3; ++mt)
                ldsm4(af[mt], st + (mbase + mt * 16 + lrow) * 72 + ks + lcol);
            #pragma unroll
            for (int mt = 0; mt < 3; ++mt)
                #pragma unroll
                for (int nt = 0; nt < 8; ++nt)
                    mma16816h(acc[mt][nt], af[mt], bf[nt]);
        }
        if (s + 2 < NIT) LOAD_STAGE(s + 2);
    }

    // ---- epilogue ----
    const int g  = lane >> 2;
    const int tg = lane & 3;
    #pragma unroll
    for (int mt = 0; mt < 3; ++mt) {
        #pragma unroll
        for (int nt = 0; nt < 8; ++nt) {
            int r0 = bm0 + mbase + mt * 16 + g;
            int r1 = r0 + 8;
            int c  = bn0 + nbase + nt * 8 + tg * 2;
            float* a4 = acc[mt][nt];
            if (MODE == 0) {
                __half2 v0 = __floats2half2_rn(a4[0], a4[1]);
                __half2 v1 = __floats2half2_rn(a4[2], a4[3]);
                if (r0 < NN) *(__half2*)&g_h1[(size_t)r0 * HID + c] = v0;
                if (r1 < NN) *(__half2*)&g_h1[(size_t)r1 * HID + c] = v1;
            } else {
                if (c < COUT) {
                    float2 v0 = make_float2(a4[0] + bias0[c], a4[1] + bias0[c + 1]);
                    float2 v1 = make_float2(a4[2] + bias0[c], a4[3] + bias0[c + 1]);
                    if (r0 < NN) {
                        *(float2*)&Cout[(size_t)r0 * COUT + c] = v0;                   // z
                        *(float2*)&Cout[(size_t)(NN + r0) * COUT + c] = v0;            // mu
                    }
                    if (r1 < NN) {
                        *(float2*)&Cout[(size_t)r1 * COUT + c] = v1;
                        *(float2*)&Cout[(size_t)(NN + r1) * COUT + c] = v1;
                    }
                } else {
                    int cs = c - COUT;
                    float2 v0 = make_float2(a4[0] + bias1[cs], a4[1] + bias1[cs + 1]);
                    float2 v1 = make_float2(a4[2] + bias1[cs], a4[3] + bias1[cs + 1]);
                    if (r0 < NN) *(float2*)&Cout[(size_t)(2 * NN + r0) * COUT + cs] = v0;  // logstd
                    if (r1 < NN) *(float2*)&Cout[(size_t)(2 * NN + r1) * COUT + cs] = v1;
                }
            }
        }
    }
    #undef LOAD_STAGE
}

// ---------------- aggregation (fp16 gather, f32 accumulate) ----------------
__global__ void __launch_bounds__(256)
k_agg1(const float* __restrict__ bias) {
    const int i = blockIdx.x;
    const int t = threadIdx.x;
    const float dv = g_dinv[i];
    const float sw = dv * dv;

    const __half2* self = (const __half2*)(g_h1 + (size_t)i * HID);
    float2 f0 = __half22float2(self[t]);
    float2 f1 = __half22float2(self[t + 256]);
    float a0 = sw * f0.x, a1 = sw * f0.y, a2 = sw * f1.x, a3 = sw * f1.y;

    const int beg = g_rowptr[i];
    const int end = g_rowptr[i + 1];
    #pragma unroll 2
    for (int e = beg; e < end; ++e) {
        const int   s = g_cols[e];
        const float w = g_wt[e];
        const __half2* r = (const __half2*)(g_h1 + (size_t)s * HID);
        float2 r0 = __half22float2(r[t]);
        float2 r1 = __half22float2(r[t + 256]);
        a0 = fmaf(w, r0.x, a0);
        a1 = fmaf(w, r0.y, a1);
        a2 = fmaf(w, r1.x, a2);
        a3 = fmaf(w, r1.y, a3);
    }
    a0 += bias[2 * t];       a0 = (a0 > 0.f) ? a0 : SLOPE * a0;
    a1 += bias[2 * t + 1];   a1 = (a1 > 0.f) ? a1 : SLOPE * a1;
    a2 += bias[2 * t + 512]; a2 = (a2 > 0.f) ? a2 : SLOPE * a2;
    a3 += bias[2 * t + 513]; a3 = (a3 > 0.f) ? a3 : SLOPE * a3;

    __half2* o = (__half2*)(g_h2 + (size_t)i * HID);
    o[t]       = __floats2half2_rn(a0, a1);
    o[t + 256] = __floats2half2_rn(a2, a3);
}

__global__ void __launch_bounds__(256)
k_agg2() {
    const int i = blockIdx.x;
    const int t = threadIdx.x;
    const float dv = g_dinv[i];
    const float sw = dv * dv;

    const __half2* self = (const __half2*)(g_h2 + (size_t)i * HID);
    float2 f0 = __half22float2(self[t]);
    float2 f1 = __half22float2(self[t + 256]);
    float a0 = sw * f0.x, a1 = sw * f0.y, a2 = sw * f1.x, a3 = sw * f1.y;

    const int beg = g_rowptr[i];
    const int end = g_rowptr[i + 1];
    #pragma unroll 2
    for (int e = beg; e < end; ++e) {
        const int   s = g_cols[e];
        const float w = g_wt[e];
        const __half2* r = (const __half2*)(g_h2 + (size_t)s * HID);
        float2 r0 = __half22float2(r[t]);
        float2 r1 = __half22float2(r[t + 256]);
        a0 = fmaf(w, r0.x, a0);
        a1 = fmaf(w, r0.y, a1);
        a2 = fmaf(w, r1.x, a2);
        a3 = fmaf(w, r1.y, a3);
    }

    __half2* o = (__half2*)(g_a2h + (size_t)i * KH);
    o[t]       = __floats2half2_rn(a0, a1);
    o[t + 256] = __floats2half2_rn(a2, a3);
}

// ---------------- launch ----------------
extern "C" void kernel_launch(void* const* d_in, const int* in_sizes, int n_in,
                              void* d_out, int out_size) {
    const float* x   = (const float*)d_in[0];
    const void*  edg = d_in[1];
    const float* W1  = (const float*)d_in[2];
    const float* b1  = (const float*)d_in[3];
    const float* Wm  = (const float*)d_in[4];
    const float* bm  = (const float*)d_in[5];
    const float* Ws  = (const float*)d_in[6];
    const float* bs  = (const float*)d_in[7];
    const float* gw  = (const float*)d_in[8];
    const float* gb  = (const float*)d_in[9];
    const float* gms = (const float*)d_in[10];
    float* out = (float*)d_out;

    // Lazily create side stream + events on the first (non-capture) call.
    static cudaStream_t s_edge = nullptr;
    static cudaEvent_t  ev_fork = nullptr, ev_w = nullptr, ev_join = nullptr;
    if (s_edge == nullptr) {
        cudaStreamCreateWithFlags(&s_edge, cudaStreamNonBlocking);
        cudaEventCreateWithFlags(&ev_fork, cudaEventDisableTiming);
        cudaEventCreateWithFlags(&ev_w,    cudaEventDisableTiming);
        cudaEventCreateWithFlags(&ev_join, cudaEventDisableTiming);
    }

    constexpr int DSMEM = (MT * 72 + 64 * 264) * 3 * 2;   // 142848 bytes
    cudaFuncSetAttribute(k_mma<0>, cudaFuncAttributeMaxDynamicSharedMemorySize, DSMEM);
    cudaFuncSetAttribute(k_mma<1>, cudaFuncAttributeMaxDynamicSharedMemorySize, DSMEM);

    // common root: zero counters/sums + dtype detect
    k_zero<<<(NN + 255) / 256, 256>>>((const int*)edg);
    cudaEventRecord(ev_fork, 0);

    // ---- side stream: weight conversion (feeds GEMMs) + edge chain (feeds aggs) ----
    cudaStreamWaitEvent(s_edge, ev_fork, 0);
    k_build_w<<<(CIN * HID / 4 + 255) / 256, 256, 0, s_edge>>>(W1, Wm, Ws);
    cudaEventRecord(ev_w, s_edge);
    k_convert<<<(EE + 255) / 256, 256, 0, s_edge>>>(edg);
    k_scan<<<1, 1024, 0, s_edge>>>();
    k_fill<<<(EE + 255) / 256, 256, 0, s_edge>>>();
    cudaEventRecord(ev_join, s_edge);

    // ---- main stream: dense chain ----
    k_stats<<<400, 256>>>(x);
    k_fin<<<(CIN + 255) / 256, 256>>>(gw, gb, gms);
    k_build_a1<<<(NN * CIN / 4 + 255) / 256, 256>>>(x);

    // layer 1: h = graphnorm(x) @ W1   (fp16 out) — needs B1 from side stream
    cudaStreamWaitEvent(0, ev_w, 0);
    dim3 g1(HID / NT2, MTILES);     // (4, 105)
    k_mma<0><<<g1, 256, DSMEM>>>(nullptr, nullptr, nullptr);

    // join: aggregations need the edge CSR
    cudaStreamWaitEvent(0, ev_join, 0);
    k_agg1<<<NN, 256>>>(b1);
    k_agg2<<<NN, 256>>>();

    // layer 2: out = A2 @ [Wm|Ws] + bias   (z = mu duplicated)
    dim3 g2(HID / NT2, MTILES);
    k_mma<1><<<g2, 256, DSMEM>>>(bm, bs, out);
}